// round 1
// baseline (speedup 1.0000x reference)
#include <cuda_runtime.h>
#include <math.h>

#define Bb 8
#define Mm 128
#define HID 256
#define NHd 8
#define Dd 32
#define NROWS_E (Bb*Mm*Mm)   // 131072
#define NROWS_N (Bb*Mm)      // 1024
#define QK_SCALE 0.17677669529663687f  // 1/sqrt(32)

// -------- scratch (device globals; no allocation allowed) --------
__device__ float g_k[(size_t)NROWS_E * HID];      // 134 MB: k projection
__device__ float g_q[NROWS_N * HID];
__device__ float g_v[NROWS_N * HID];
__device__ float g_S[Bb * NHd * Mm * Mm];         // scores
__device__ float g_msg[Bb * NHd * Mm * Mm];       // message
__device__ float g_nodeh[NROWS_N * HID];
__device__ float g_rmax[Bb * NHd * Mm];
__device__ float g_rsum[Bb * NHd * Mm];
__device__ float g_cmax[Bb * NHd * Mm];
__device__ float g_csum[Bb * NHd * Mm];

__device__ __forceinline__ float mish_f(float x) {
    float sp = (x > 20.f) ? x : log1pf(__expf(x));
    return x * tanhf(sp);
}

// ============================================================
// Tiled SGEMM: C[r,c] = act( sum_e A'[r,e] * W[c,e] + bias[c] )
// A' = A (optionally scaled per-row-per-head by g_msg for the edge output GEMM)
// BM=128, BN=64, BK=16, 256 threads, 8x4 per thread.
// ============================================================
template<bool MSG, bool ACT>
__global__ void __launch_bounds__(256)
gemm_kernel(const float* __restrict__ A, const float* __restrict__ W,
            const float* __restrict__ bias, float* __restrict__ C)
{
    __shared__ __align__(16) float As[16][132];
    __shared__ __align__(16) float Bs[16][68];

    const int row0 = blockIdx.x * 128;
    const int col0 = blockIdx.y * 64;
    const int t  = threadIdx.x;
    const int tx = t & 15;
    const int ty = t >> 4;
    const int lr = t >> 2;
    const int lc = (t & 3) << 2;

    const int gr1 = row0 + lr;
    const int gr2 = gr1 + 64;

    int mbase1 = 0, mbase2 = 0;
    if (MSG) {
        int b1 = gr1 >> 14, m1 = (gr1 >> 7) & 127, n1 = gr1 & 127;
        int b2 = gr2 >> 14, m2 = (gr2 >> 7) & 127, n2 = gr2 & 127;
        mbase1 = b1 * 131072 + m1 * 128 + n1;   // + h*16384
        mbase2 = b2 * 131072 + m2 * 128 + n2;
    }

    float acc[8][4];
    #pragma unroll
    for (int i = 0; i < 8; i++)
        #pragma unroll
        for (int j = 0; j < 4; j++) acc[i][j] = 0.f;

    for (int k0 = 0; k0 < HID; k0 += 16) {
        float4 a1 = *(const float4*)(A + (size_t)gr1 * HID + k0 + lc);
        float4 a2 = *(const float4*)(A + (size_t)gr2 * HID + k0 + lc);
        if (MSG) {
            int h = (k0 + lc) >> 5;
            float s1 = g_msg[mbase1 + h * 16384];
            float s2 = g_msg[mbase2 + h * 16384];
            a1.x *= s1; a1.y *= s1; a1.z *= s1; a1.w *= s1;
            a2.x *= s2; a2.y *= s2; a2.z *= s2; a2.w *= s2;
        }
        As[lc + 0][lr] = a1.x; As[lc + 1][lr] = a1.y;
        As[lc + 2][lr] = a1.z; As[lc + 3][lr] = a1.w;
        As[lc + 0][lr + 64] = a2.x; As[lc + 1][lr + 64] = a2.y;
        As[lc + 2][lr + 64] = a2.z; As[lc + 3][lr + 64] = a2.w;

        float4 b4 = *(const float4*)(W + (size_t)(col0 + lr) * HID + k0 + lc);
        Bs[lc + 0][lr] = b4.x; Bs[lc + 1][lr] = b4.y;
        Bs[lc + 2][lr] = b4.z; Bs[lc + 3][lr] = b4.w;
        __syncthreads();

        #pragma unroll
        for (int kk = 0; kk < 16; kk++) {
            float4 alo = *(const float4*)&As[kk][ty * 8];
            float4 ahi = *(const float4*)&As[kk][ty * 8 + 4];
            float4 bv  = *(const float4*)&Bs[kk][tx * 4];
            float av[8] = {alo.x, alo.y, alo.z, alo.w, ahi.x, ahi.y, ahi.z, ahi.w};
            float bw[4] = {bv.x, bv.y, bv.z, bv.w};
            #pragma unroll
            for (int i = 0; i < 8; i++)
                #pragma unroll
                for (int j = 0; j < 4; j++)
                    acc[i][j] = fmaf(av[i], bw[j], acc[i][j]);
        }
        __syncthreads();
    }

    float4 bb = *(const float4*)(bias + col0 + tx * 4);
    float bias4[4] = {bb.x, bb.y, bb.z, bb.w};
    #pragma unroll
    for (int i = 0; i < 8; i++) {
        float v0 = acc[i][0] + bias4[0];
        float v1 = acc[i][1] + bias4[1];
        float v2 = acc[i][2] + bias4[2];
        float v3 = acc[i][3] + bias4[3];
        if (ACT) { v0 = mish_f(v0); v1 = mish_f(v1); v2 = mish_f(v2); v3 = mish_f(v3); }
        float4 o; o.x = v0; o.y = v1; o.z = v2; o.w = v3;
        *(float4*)(C + (size_t)(row0 + ty * 8 + i) * HID + col0 + tx * 4) = o;
    }
}

// ============================================================
// Scores: S[b,h,m,n] = scale * sum_d q[b,m,h*32+d] * k[b,m,n,h*32+d]
// one block per (b,m); stage k rows through smem for coalesced reads.
// ============================================================
__global__ void __launch_bounds__(256) scores_kernel()
{
    __shared__ float qs[256];
    __shared__ __align__(16) float ks[16][260];
    const int bm = blockIdx.x;          // b*128 + m
    const int b = bm >> 7;
    const int m = bm & 127;
    const int t = threadIdx.x;

    qs[t] = g_q[bm * 256 + t];
    __syncthreads();

    const float* kbase = g_k + (size_t)bm * (128 * 256);
    const int h = t >> 4, nl = t & 15;  // used when t < 128

    for (int n0 = 0; n0 < 128; n0 += 16) {
        #pragma unroll
        for (int r = 0; r < 4; r++) {
            int idx4 = t + 256 * r;           // 0..1023 float4s
            int nn = idx4 >> 6;               // 64 float4 per row
            int cc = (idx4 & 63) * 4;
            *(float4*)&ks[nn][cc] =
                *(const float4*)(kbase + (size_t)(n0 + nn) * 256 + cc);
        }
        __syncthreads();
        if (t < 128) {
            float acc = 0.f;
            const float* kr = &ks[nl][h * 32];
            const float* qr = &qs[h * 32];
            #pragma unroll
            for (int d = 0; d < 32; d++) acc = fmaf(qr[d], kr[d], acc);
            g_S[((size_t)(b * 8 + h) * 128 + m) * 128 + n0 + nl] = acc * QK_SCALE;
        }
        __syncthreads();
    }
}

// ============================================================
// Masked online softmax stats: row stats (out_attn) and column
// stats (in_attn = softmax over first index of S at fixed column).
// ============================================================
__global__ void __launch_bounds__(128) stats_kernel(const float* __restrict__ mask)
{
    const int bh = blockIdx.x;
    const int b = bh >> 3;
    const int t = threadIdx.x;
    const float* Sb = g_S + (size_t)bh * 16384;
    __shared__ float mks[128];
    mks[t] = mask[b * 128 + t];
    __syncthreads();

    float mx = -1e30f, sm = 0.f;
    for (int j = 0; j < 128; j++) {
        if (mks[j] != 0.f) {
            float x = Sb[t * 128 + j];
            if (x > mx) { sm = sm * expf(mx - x) + 1.f; mx = x; }
            else sm += expf(x - mx);
        }
    }
    g_rmax[bh * 128 + t] = mx;
    g_rsum[bh * 128 + t] = sm;

    mx = -1e30f; sm = 0.f;
    for (int i = 0; i < 128; i++) {
        if (mks[i] != 0.f) {
            float x = Sb[i * 128 + t];
            if (x > mx) { sm = sm * expf(mx - x) + 1.f; mx = x; }
            else sm += expf(x - mx);
        }
    }
    g_cmax[bh * 128 + t] = mx;
    g_csum[bh * 128 + t] = sm;
}

// ============================================================
// message[i,j] = (out_attn[i,j] + in_attn[i,j] - delta_ij*out_attn[i,i])
//              * exp(-lam*dist[b,i,j]) * mask_j
// at i==j this collapses to in_attn[i,i] * dm.
// in_attn[i,j] = mask_j * exp(S[j,i]-cmax_i)/csum_i
// ============================================================
__global__ void __launch_bounds__(256)
message_kernel(const float* __restrict__ dist, const float* __restrict__ mask,
               const float* __restrict__ lamp)
{
    const int bh = blockIdx.x;
    const int b = bh >> 3;
    const int t = threadIdx.x;
    const float lam = lamp[0];
    __shared__ float rm[128], rs[128], cm[128], cs[128], mks[128];
    if (t < 128) {
        rm[t] = g_rmax[bh * 128 + t]; rs[t] = 1.f / g_rsum[bh * 128 + t];
        cm[t] = g_cmax[bh * 128 + t]; cs[t] = 1.f / g_csum[bh * 128 + t];
        mks[t] = mask[b * 128 + t];
    }
    __syncthreads();
    const float* Sb = g_S + (size_t)bh * 16384;
    const float* db = dist + (size_t)b * 16384;
    float* mb = g_msg + (size_t)bh * 16384;
    for (int idx = t; idx < 16384; idx += 256) {
        int i = idx >> 7, j = idx & 127;
        float outv = 0.f;
        if (mks[j] != 0.f) {
            float o  = expf(Sb[idx] - rm[i]) * rs[i];
            float in = expf(Sb[j * 128 + i] - cm[i]) * cs[i];
            float val = (i == j) ? in : (o + in);
            outv = val * expf(-lam * db[idx]);
        }
        mb[idx] = outv;
    }
}

// ============================================================
// node_hidden[b,m,h*32+d] = sum_n msg[b,h,m,n] * v[b,n,h*32+d]
// one block per (b,h); v_h slice staged in smem.
// ============================================================
__global__ void __launch_bounds__(256) nodeh_kernel()
{
    const int bh = blockIdx.x;
    const int b = bh >> 3, h = bh & 7;
    const int t = threadIdx.x;
    __shared__ __align__(16) float vs[128 * 32];
    #pragma unroll
    for (int r = 0; r < 4; r++) {
        int idx4 = t + 256 * r;       // 1024 float4s
        int n = idx4 >> 3;            // 8 float4 per n-row
        int c = (idx4 & 7) * 4;
        *(float4*)&vs[n * 32 + c] =
            *(const float4*)(g_v + (size_t)(b * 128 + n) * 256 + h * 32 + c);
    }
    __syncthreads();
    const int m = t & 127;
    const int dbase = (t >> 7) * 16;
    const float* mrow = g_msg + (size_t)bh * 16384 + m * 128;
    float acc[16];
    #pragma unroll
    for (int d = 0; d < 16; d++) acc[d] = 0.f;
    for (int n = 0; n < 128; n++) {
        float w = mrow[n];
        const float* vr = &vs[n * 32 + dbase];
        #pragma unroll
        for (int d = 0; d < 16; d++) acc[d] = fmaf(w, vr[d], acc[d]);
    }
    float* outp = g_nodeh + (size_t)(b * 128 + m) * 256 + h * 32 + dbase;
    #pragma unroll
    for (int d = 0; d < 16; d++) outp[d] = acc[d];
}

// ============================================================
extern "C" void kernel_launch(void* const* d_in, const int* in_sizes, int n_in,
                              void* d_out, int out_size)
{
    const float* node = (const float*)d_in[0];
    const float* edge = (const float*)d_in[1];
    const float* dist = (const float*)d_in[2];
    const float* mask = (const float*)d_in[3];
    const float* lam  = (const float*)d_in[4];
    const float* Wq = (const float*)d_in[5];  const float* bq = (const float*)d_in[6];
    const float* Wk = (const float*)d_in[7];  const float* bk = (const float*)d_in[8];
    const float* Wv = (const float*)d_in[9];  const float* bv = (const float*)d_in[10];
    const float* Wn = (const float*)d_in[11]; const float* bn = (const float*)d_in[12];
    const float* We = (const float*)d_in[13]; const float* be = (const float*)d_in[14];

    float* out = (float*)d_out;
    float* node_out = out;                                  // 8*128*256
    float* edge_out = out + (size_t)NROWS_N * HID;          // 8*128*128*256

    float *pk, *pq, *pv, *pnh;
    cudaGetSymbolAddress((void**)&pk, g_k);
    cudaGetSymbolAddress((void**)&pq, g_q);
    cudaGetSymbolAddress((void**)&pv, g_v);
    cudaGetSymbolAddress((void**)&pnh, g_nodeh);

    dim3 gN(NROWS_N / 128, HID / 64);   // (8, 4)
    dim3 gE(NROWS_E / 128, HID / 64);   // (1024, 4)

    gemm_kernel<false, false><<<gN, 256>>>(node, Wq, bq, pq);
    gemm_kernel<false, false><<<gN, 256>>>(node, Wv, bv, pv);
    gemm_kernel<false, false><<<gE, 256>>>(edge, Wk, bk, pk);
    scores_kernel<<<NROWS_N, 256>>>();
    stats_kernel<<<Bb * NHd, 128>>>(mask);
    message_kernel<<<Bb * NHd, 256>>>(dist, mask, lam);
    nodeh_kernel<<<Bb * NHd, 256>>>();
    gemm_kernel<false, true><<<gN, 256>>>(pnh, Wn, bn, node_out);
    gemm_kernel<true,  true><<<gE, 256>>>(pk, We, be, edge_out);
}

// round 3
// speedup vs baseline: 1.7244x; 1.7244x over previous
#include <cuda_runtime.h>
#include <cuda_bf16.h>
#include <math.h>
#include <cstdint>

#define Bb 8
#define Mm 128
#define HID 256
#define NHd 8
#define NROWS_E (Bb*Mm*Mm)   // 131072
#define NROWS_N (Bb*Mm)      // 1024
#define QK_SCALE 0.17677669529663687f  // 1/sqrt(32)

// -------- scratch (device globals; no allocation allowed) --------
__device__ float g_k[(size_t)NROWS_E * HID];      // 134 MB
__device__ float g_q[NROWS_N * HID];
__device__ float g_v[NROWS_N * HID];
__device__ float g_S[Bb * NHd * Mm * Mm];
__device__ float g_msg[Bb * NHd * Mm * Mm];
__device__ float g_nodeh[NROWS_N * HID];
__device__ float g_rmax[Bb * NHd * Mm];
__device__ float g_rsum[Bb * NHd * Mm];
__device__ float g_cmax[Bb * NHd * Mm];
__device__ float g_csum[Bb * NHd * Mm];
__device__ __align__(16) __nv_bfloat16 g_wk2[2 * HID * HID];  // [hi|lo]
__device__ __align__(16) __nv_bfloat16 g_we2[2 * HID * HID];

__device__ __forceinline__ float mish_f(float x) {
    float sp = (x > 20.f) ? x : log1pf(__expf(x));
    return x * tanhf(sp);
}

__device__ __forceinline__ uint32_t smem_u32(const void* p) {
    uint32_t a;
    asm("{ .reg .u64 t; cvta.to.shared.u64 t, %1; cvt.u32.u64 %0, t; }" : "=r"(a) : "l"(p));
    return a;
}
__device__ __forceinline__ void ldsm4(uint32_t* r, uint32_t addr) {
    asm volatile("ldmatrix.sync.aligned.m8n8.x4.shared.b16 {%0,%1,%2,%3}, [%4];"
        : "=r"(r[0]), "=r"(r[1]), "=r"(r[2]), "=r"(r[3]) : "r"(addr));
}
__device__ __forceinline__ void mma_bf16(float* d, const uint32_t* a, const uint32_t* b) {
    asm volatile("mma.sync.aligned.m16n8k16.row.col.f32.bf16.bf16.f32 "
        "{%0,%1,%2,%3}, {%4,%5,%6,%7}, {%8,%9}, {%0,%1,%2,%3};"
        : "+f"(d[0]), "+f"(d[1]), "+f"(d[2]), "+f"(d[3])
        : "r"(a[0]), "r"(a[1]), "r"(a[2]), "r"(a[3]), "r"(b[0]), "r"(b[1]));
}
#define CP16(dst, src) asm volatile("cp.async.cg.shared.global [%0], [%1], 16;" :: "r"(dst), "l"(src))
#define CP_COMMIT() asm volatile("cp.async.commit_group;" ::: "memory")
#define CP_WAIT0()  asm volatile("cp.async.wait_group 0;" ::: "memory")

// ============================================================
// W split prep: hi = bf16_rn(w), lo = bf16_rn(w - hi)
// ============================================================
__global__ void __launch_bounds__(256) prep_w_kernel(const float* __restrict__ Wk,
                                                     const float* __restrict__ We)
{
    int t = blockIdx.x * 256 + threadIdx.x;   // 65536 total
    float a = Wk[t];
    __nv_bfloat16 h = __float2bfloat16_rn(a);
    g_wk2[t] = h;
    g_wk2[65536 + t] = __float2bfloat16_rn(a - __bfloat162float(h));
    float b = We[t];
    h = __float2bfloat16_rn(b);
    g_we2[t] = h;
    g_we2[65536 + t] = __float2bfloat16_rn(b - __bfloat162float(h));
}

// ============================================================
// mma.sync split-bf16 GEMM: C[131072,256] = act(A' @ W^T + bias)
// A' = A optionally scaled per (row, head=k/32) by g_msg.
// Tiles: BM=128, BN=128, BK=32; 8 warps (warp tile 32x64).
// Per k-chunk, 3 mma terms: Ahi*Whi + Alo*Whi + Ahi*Wlo.
// SMEM per stage: A_hi, A_lo, B_hi, B_lo each 128 rows x 80B.
// ============================================================
#define TG_STAGE   40960
#define TG_ALO     10240
#define TG_BHI     20480
#define TG_BLO     30720
#define TG_SMEM    (2 * TG_STAGE)

template<bool MSG, bool ACT>
__global__ void __launch_bounds__(256, 2) tgemm_kernel(
    const float* __restrict__ A, const __nv_bfloat16* __restrict__ W2,
    const float* __restrict__ bias, float* __restrict__ C)
{
    extern __shared__ char smem[];
    const uint32_t sb = smem_u32(smem);
    const int tid = threadIdx.x;
    const int wid = tid >> 5, lane = tid & 31;
    const int wm = wid >> 1, wn = wid & 1;
    const int col0 = blockIdx.x * 128;
    const int r0 = blockIdx.y * 128;

    const int arow = tid >> 1, ahalf = tid & 1;

    // msg base for this thread's A row (valid when MSG)
    int mbase = 0;
    if (MSG) {
        int b = r0 >> 14, m = (r0 >> 7) & 127;
        mbase = (b << 17) + (m << 7) + arow;
    }

    const float* gA = A + (size_t)(r0 + arow) * 256 + ahalf * 16;
    const __nv_bfloat16* gWh = W2 + (size_t)(col0 + arow) * 256 + ahalf * 16;
    const __nv_bfloat16* gWl = gWh + 65536;
    char* sA = smem + arow * 80 + ahalf * 32;

    float av[16];
    float s_cur = 1.f, s_nxt = 1.f;

    auto fillW = [&](int c, int stg) {
        uint32_t d = sb + stg * TG_STAGE + TG_BHI + arow * 80 + ahalf * 32;
        const char* sh = (const char*)(gWh + c * 32);
        const char* sl = (const char*)(gWl + c * 32);
        CP16(d, sh); CP16(d + 16, sh + 16);
        CP16(d + TG_BLO - TG_BHI, sl); CP16(d + TG_BLO - TG_BHI + 16, sl + 16);
        CP_COMMIT();
    };
    auto ldA = [&](int c, float* v, float& s) {
        const float* p = gA + c * 32;
        *(float4*)(v + 0)  = *(const float4*)(p + 0);
        *(float4*)(v + 4)  = *(const float4*)(p + 4);
        *(float4*)(v + 8)  = *(const float4*)(p + 8);
        *(float4*)(v + 12) = *(const float4*)(p + 12);
        if (MSG) s = g_msg[mbase + (c << 14)];
    };
    auto stA = [&](int stg, const float* v, float s) {
        uint32_t hw[8], lw[8];
        #pragma unroll
        for (int p = 0; p < 8; p++) {
            float v0 = v[2 * p] * s, v1 = v[2 * p + 1] * s;
            __nv_bfloat162 h = __floats2bfloat162_rn(v0, v1);
            __nv_bfloat162 l = __floats2bfloat162_rn(
                v0 - __bfloat162float(h.x), v1 - __bfloat162float(h.y));
            hw[p] = *(uint32_t*)&h; lw[p] = *(uint32_t*)&l;
        }
        char* d = sA + stg * TG_STAGE;
        *(uint4*)d        = make_uint4(hw[0], hw[1], hw[2], hw[3]);
        *(uint4*)(d + 16) = make_uint4(hw[4], hw[5], hw[6], hw[7]);
        char* d2 = d + TG_ALO;
        *(uint4*)d2        = make_uint4(lw[0], lw[1], lw[2], lw[3]);
        *(uint4*)(d2 + 16) = make_uint4(lw[4], lw[5], lw[6], lw[7]);
    };

    float acc[2][8][4];
    #pragma unroll
    for (int i = 0; i < 2; i++)
        #pragma unroll
        for (int j = 0; j < 8; j++)
            #pragma unroll
            for (int q = 0; q < 4; q++) acc[i][j][q] = 0.f;

    // ldmatrix address templates
    const uint32_t aAddr0 = sb + (wm * 32 + (lane & 15)) * 80 + (lane >> 4) * 16;
    const uint32_t bAddr0 = sb + TG_BHI +
        (wn * 64 + ((lane >> 4) & 1) * 8 + (lane & 7)) * 80 + ((lane >> 3) & 1) * 16;

    // prologue: chunk 0
    fillW(0, 0);
    ldA(0, av, s_cur);
    stA(0, av, s_cur);
    CP_WAIT0();
    __syncthreads();

    #pragma unroll 1
    for (int c = 0; c < 8; c++) {
        const int stg = c & 1, nst = stg ^ 1;
        if (c < 7) {
            fillW(c + 1, nst);
            ldA(c + 1, av, s_nxt);
        }
        const uint32_t abase = aAddr0 + stg * TG_STAGE;
        const uint32_t bbase = bAddr0 + stg * TG_STAGE;
        #pragma unroll
        for (int ks = 0; ks < 2; ks++) {
            const uint32_t koff = ks * 32;
            uint32_t bh[16], ah[8], al[8];
            #pragma unroll
            for (int ng = 0; ng < 4; ng++)
                ldsm4(&bh[ng * 4], bbase + ng * 16 * 80 + koff);
            #pragma unroll
            for (int mt = 0; mt < 2; mt++)
                ldsm4(&ah[mt * 4], abase + mt * 16 * 80 + koff);
            #pragma unroll
            for (int mt = 0; mt < 2; mt++)
                #pragma unroll
                for (int nt = 0; nt < 8; nt++)
                    mma_bf16(acc[mt][nt], &ah[mt * 4], &bh[(nt >> 1) * 4 + (nt & 1) * 2]);
            #pragma unroll
            for (int mt = 0; mt < 2; mt++)
                ldsm4(&al[mt * 4], abase + TG_ALO + mt * 16 * 80 + koff);
            #pragma unroll
            for (int mt = 0; mt < 2; mt++)
                #pragma unroll
                for (int nt = 0; nt < 8; nt++)
                    mma_bf16(acc[mt][nt], &al[mt * 4], &bh[(nt >> 1) * 4 + (nt & 1) * 2]);
            #pragma unroll
            for (int ng = 0; ng < 4; ng++)
                ldsm4(&bh[ng * 4], bbase + (TG_BLO - TG_BHI) + ng * 16 * 80 + koff);
            #pragma unroll
            for (int mt = 0; mt < 2; mt++)
                #pragma unroll
                for (int nt = 0; nt < 8; nt++)
                    mma_bf16(acc[mt][nt], &ah[mt * 4], &bh[(nt >> 1) * 4 + (nt & 1) * 2]);
        }
        if (c < 7) {
            stA(nst, av, s_nxt);
            CP_WAIT0();
            __syncthreads();
        }
    }

    // epilogue: bias (+mish), direct float2 stores
    #pragma unroll
    for (int nt = 0; nt < 8; nt++) {
        const int col = col0 + wn * 64 + nt * 8 + (lane & 3) * 2;
        const float b0 = bias[col], b1 = bias[col + 1];
        #pragma unroll
        for (int mt = 0; mt < 2; mt++) {
            int row = r0 + wm * 32 + mt * 16 + (lane >> 2);
            float v0 = acc[mt][nt][0] + b0, v1 = acc[mt][nt][1] + b1;
            float v2 = acc[mt][nt][2] + b0, v3 = acc[mt][nt][3] + b1;
            if (ACT) { v0 = mish_f(v0); v1 = mish_f(v1); v2 = mish_f(v2); v3 = mish_f(v3); }
            float2 p0; p0.x = v0; p0.y = v1;
            float2 p1; p1.x = v2; p1.y = v3;
            *(float2*)(C + (size_t)row * 256 + col) = p0;
            *(float2*)(C + (size_t)(row + 8) * 256 + col) = p1;
        }
    }
}

// ============================================================
// fp32 SGEMM for the small (1024-row) projections
// ============================================================
template<bool ACT>
__global__ void __launch_bounds__(256)
gemm_kernel(const float* __restrict__ A, const float* __restrict__ W,
            const float* __restrict__ bias, float* __restrict__ C)
{
    __shared__ __align__(16) float As[16][132];
    __shared__ __align__(16) float Bs[16][68];

    const int row0 = blockIdx.x * 128;
    const int col0 = blockIdx.y * 64;
    const int t  = threadIdx.x;
    const int tx = t & 15;
    const int ty = t >> 4;
    const int lr = t >> 2;
    const int lc = (t & 3) << 2;
    const int gr1 = row0 + lr;
    const int gr2 = gr1 + 64;

    float acc[8][4];
    #pragma unroll
    for (int i = 0; i < 8; i++)
        #pragma unroll
        for (int j = 0; j < 4; j++) acc[i][j] = 0.f;

    for (int k0 = 0; k0 < HID; k0 += 16) {
        float4 a1 = *(const float4*)(A + (size_t)gr1 * HID + k0 + lc);
        float4 a2 = *(const float4*)(A + (size_t)gr2 * HID + k0 + lc);
        As[lc + 0][lr] = a1.x; As[lc + 1][lr] = a1.y;
        As[lc + 2][lr] = a1.z; As[lc + 3][lr] = a1.w;
        As[lc + 0][lr + 64] = a2.x; As[lc + 1][lr + 64] = a2.y;
        As[lc + 2][lr + 64] = a2.z; As[lc + 3][lr + 64] = a2.w;
        float4 b4 = *(const float4*)(W + (size_t)(col0 + lr) * HID + k0 + lc);
        Bs[lc + 0][lr] = b4.x; Bs[lc + 1][lr] = b4.y;
        Bs[lc + 2][lr] = b4.z; Bs[lc + 3][lr] = b4.w;
        __syncthreads();
        #pragma unroll
        for (int kk = 0; kk < 16; kk++) {
            float4 alo = *(const float4*)&As[kk][ty * 8];
            float4 ahi = *(const float4*)&As[kk][ty * 8 + 4];
            float4 bv  = *(const float4*)&Bs[kk][tx * 4];
            float avv[8] = {alo.x, alo.y, alo.z, alo.w, ahi.x, ahi.y, ahi.z, ahi.w};
            float bw[4] = {bv.x, bv.y, bv.z, bv.w};
            #pragma unroll
            for (int i = 0; i < 8; i++)
                #pragma unroll
                for (int j = 0; j < 4; j++)
                    acc[i][j] = fmaf(avv[i], bw[j], acc[i][j]);
        }
        __syncthreads();
    }

    float4 bb = *(const float4*)(bias + col0 + tx * 4);
    float bias4[4] = {bb.x, bb.y, bb.z, bb.w};
    #pragma unroll
    for (int i = 0; i < 8; i++) {
        float v0 = acc[i][0] + bias4[0];
        float v1 = acc[i][1] + bias4[1];
        float v2 = acc[i][2] + bias4[2];
        float v3 = acc[i][3] + bias4[3];
        if (ACT) { v0 = mish_f(v0); v1 = mish_f(v1); v2 = mish_f(v2); v3 = mish_f(v3); }
        float4 o; o.x = v0; o.y = v1; o.z = v2; o.w = v3;
        *(float4*)(C + (size_t)(row0 + ty * 8 + i) * HID + col0 + tx * 4) = o;
    }
}

// ============================================================
// Scores: S[b,h,m,n] = scale * q[b,m,h].k[b,m,n,h]
// ============================================================
__global__ void __launch_bounds__(256) scores_kernel()
{
    __shared__ float qs[256];
    __shared__ __align__(16) float ks[16][260];
    const int bm = blockIdx.x;
    const int b = bm >> 7;
    const int m = bm & 127;
    const int t = threadIdx.x;

    qs[t] = g_q[bm * 256 + t];
    __syncthreads();

    const float* kbase = g_k + (size_t)bm * (128 * 256);
    const int h = t >> 4, nl = t & 15;

    for (int n0 = 0; n0 < 128; n0 += 16) {
        #pragma unroll
        for (int r = 0; r < 4; r++) {
            int idx4 = t + 256 * r;
            int nn = idx4 >> 6;
            int cc = (idx4 & 63) * 4;
            *(float4*)&ks[nn][cc] = *(const float4*)(kbase + (size_t)(n0 + nn) * 256 + cc);
        }
        __syncthreads();
        if (t < 128) {
            float acc = 0.f;
            const float* kr = &ks[nl][h * 32];
            const float* qr = &qs[h * 32];
            #pragma unroll
            for (int d = 0; d < 32; d++) acc = fmaf(qr[d], kr[d], acc);
            g_S[((size_t)(b * 8 + h) * 128 + m) * 128 + n0 + nl] = acc * QK_SCALE;
        }
        __syncthreads();
    }
}

__global__ void __launch_bounds__(128) stats_kernel(const float* __restrict__ mask)
{
    const int bh = blockIdx.x;
    const int b = bh >> 3;
    const int t = threadIdx.x;
    const float* Sb = g_S + (size_t)bh * 16384;
    __shared__ float mks[128];
    mks[t] = mask[b * 128 + t];
    __syncthreads();

    float mx = -1e30f, sm = 0.f;
    for (int j = 0; j < 128; j++) {
        if (mks[j] != 0.f) {
            float x = Sb[t * 128 + j];
            if (x > mx) { sm = sm * expf(mx - x) + 1.f; mx = x; }
            else sm += expf(x - mx);
        }
    }
    g_rmax[bh * 128 + t] = mx;
    g_rsum[bh * 128 + t] = sm;

    mx = -1e30f; sm = 0.f;
    for (int i = 0; i < 128; i++) {
        if (mks[i] != 0.f) {
            float x = Sb[i * 128 + t];
            if (x > mx) { sm = sm * expf(mx - x) + 1.f; mx = x; }
            else sm += expf(x - mx);
        }
    }
    g_cmax[bh * 128 + t] = mx;
    g_csum[bh * 128 + t] = sm;
}

__global__ void __launch_bounds__(256)
message_kernel(const float* __restrict__ dist, const float* __restrict__ mask,
               const float* __restrict__ lamp)
{
    const int bh = blockIdx.x;
    const int b = bh >> 3;
    const int t = threadIdx.x;
    const float lam = lamp[0];
    __shared__ float rm[128], rs[128], cm[128], cs[128], mks[128];
    if (t < 128) {
        rm[t] = g_rmax[bh * 128 + t]; rs[t] = 1.f / g_rsum[bh * 128 + t];
        cm[t] = g_cmax[bh * 128 + t]; cs[t] = 1.f / g_csum[bh * 128 + t];
        mks[t] = mask[b * 128 + t];
    }
    __syncthreads();
    const float* Sb = g_S + (size_t)bh * 16384;
    const float* db = dist + (size_t)b * 16384;
    float* mb = g_msg + (size_t)bh * 16384;
    for (int idx = t; idx < 16384; idx += 256) {
        int i = idx >> 7, j = idx & 127;
        float outv = 0.f;
        if (mks[j] != 0.f) {
            float o  = expf(Sb[idx] - rm[i]) * rs[i];
            float in = expf(Sb[j * 128 + i] - cm[i]) * cs[i];
            float val = (i == j) ? in : (o + in);
            outv = val * expf(-lam * db[idx]);
        }
        mb[idx] = outv;
    }
}

__global__ void __launch_bounds__(256) nodeh_kernel()
{
    const int bh = blockIdx.x;
    const int b = bh >> 3, h = bh & 7;
    const int t = threadIdx.x;
    __shared__ __align__(16) float vs[128 * 32];
    #pragma unroll
    for (int r = 0; r < 4; r++) {
        int idx4 = t + 256 * r;
        int n = idx4 >> 3;
        int c = (idx4 & 7) * 4;
        *(float4*)&vs[n * 32 + c] =
            *(const float4*)(g_v + (size_t)(b * 128 + n) * 256 + h * 32 + c);
    }
    __syncthreads();
    const int m = t & 127;
    const int dbase = (t >> 7) * 16;
    const float* mrow = g_msg + (size_t)bh * 16384 + m * 128;
    float acc[16];
    #pragma unroll
    for (int d = 0; d < 16; d++) acc[d] = 0.f;
    for (int n = 0; n < 128; n++) {
        float w = mrow[n];
        const float* vr = &vs[n * 32 + dbase];
        #pragma unroll
        for (int d = 0; d < 16; d++) acc[d] = fmaf(w, vr[d], acc[d]);
    }
    float* outp = g_nodeh + (size_t)(b * 128 + m) * 256 + h * 32 + dbase;
    #pragma unroll
    for (int d = 0; d < 16; d++) outp[d] = acc[d];
}

// ============================================================
extern "C" void kernel_launch(void* const* d_in, const int* in_sizes, int n_in,
                              void* d_out, int out_size)
{
    const float* node = (const float*)d_in[0];
    const float* edge = (const float*)d_in[1];
    const float* dist = (const float*)d_in[2];
    const float* mask = (const float*)d_in[3];
    const float* lam  = (const float*)d_in[4];
    const float* Wq = (const float*)d_in[5];  const float* bq = (const float*)d_in[6];
    const float* Wk = (const float*)d_in[7];  const float* bk = (const float*)d_in[8];
    const float* Wv = (const float*)d_in[9];  const float* bv = (const float*)d_in[10];
    const float* Wn = (const float*)d_in[11]; const float* bn = (const float*)d_in[12];
    const float* We = (const float*)d_in[13]; const float* be = (const float*)d_in[14];

    float* out = (float*)d_out;
    float* node_out = out;
    float* edge_out = out + (size_t)NROWS_N * HID;

    float *pk, *pq, *pv, *pnh;
    __nv_bfloat16 *pwk2, *pwe2;
    cudaGetSymbolAddress((void**)&pk, g_k);
    cudaGetSymbolAddress((void**)&pq, g_q);
    cudaGetSymbolAddress((void**)&pv, g_v);
    cudaGetSymbolAddress((void**)&pnh, g_nodeh);
    cudaGetSymbolAddress((void**)&pwk2, g_wk2);
    cudaGetSymbolAddress((void**)&pwe2, g_we2);

    cudaFuncSetAttribute(tgemm_kernel<false, false>,
                         cudaFuncAttributeMaxDynamicSharedMemorySize, TG_SMEM);
    cudaFuncSetAttribute(tgemm_kernel<true, true>,
                         cudaFuncAttributeMaxDynamicSharedMemorySize, TG_SMEM);

    dim3 gN(NROWS_N / 128, HID / 64);   // (8, 4)
    dim3 gT(2, NROWS_E / 128);          // (colblocks=2, rowblocks=1024)

    prep_w_kernel<<<256, 256>>>(Wk, We);
    gemm_kernel<false><<<gN, 256>>>(node, Wq, bq, pq);
    gemm_kernel<false><<<gN, 256>>>(node, Wv, bv, pv);
    tgemm_kernel<false, false><<<gT, 256, TG_SMEM>>>(edge, pwk2, bk, pk);
    scores_kernel<<<NROWS_N, 256>>>();
    stats_kernel<<<Bb * NHd, 128>>>(mask);
    message_kernel<<<Bb * NHd, 256>>>(dist, mask, lam);
    nodeh_kernel<<<Bb * NHd, 256>>>();
    gemm_kernel<true><<<gN, 256>>>(pnh, Wn, bn, node_out);
    tgemm_kernel<true, true><<<gT, 256, TG_SMEM>>>(pk, pwe2, be, edge_out);
}

// round 4
// speedup vs baseline: 2.1542x; 1.2492x over previous
#include <cuda_runtime.h>
#include <cuda_fp16.h>
#include <math.h>
#include <cstdint>

#define Bb 8
#define Mm 128
#define HID 256
#define NROWS_E (Bb*Mm*Mm)   // 131072
#define NROWS_N (Bb*Mm)      // 1024
#define QK_SCALE 0.17677669529663687f  // 1/sqrt(32)

// -------- scratch (device globals; no allocation allowed) --------
__device__ float g_k[(size_t)NROWS_E * HID];          // 134 MB
__device__ __align__(16) __half g_a16[(size_t)NROWS_E * HID];  // 67 MB fp16 A operand
__device__ float g_q[NROWS_N * HID];
__device__ float g_v[NROWS_N * HID];
__device__ float g_S[64 * 128 * 128];
__device__ float g_msg[64 * 128 * 128];
__device__ float g_nodeh[NROWS_N * HID];
__device__ __align__(16) __half g_wk2[2 * HID * HID];  // [hi | lo]
__device__ __align__(16) __half g_we2[2 * HID * HID];

__device__ __forceinline__ float mish_f(float x) {
    if (x > 20.f) return x;
    float t = 1.f + __expf(x);
    float t2 = t * t;
    return x * __fdividef(t2 - 1.f, t2 + 1.f);
}

__device__ __forceinline__ uint32_t smem_u32(const void* p) {
    uint32_t a;
    asm("{ .reg .u64 t; cvta.to.shared.u64 t, %1; cvt.u32.u64 %0, t; }" : "=r"(a) : "l"(p));
    return a;
}
__device__ __forceinline__ void ldsm4(uint32_t* r, uint32_t addr) {
    asm volatile("ldmatrix.sync.aligned.m8n8.x4.shared.b16 {%0,%1,%2,%3}, [%4];"
        : "=r"(r[0]), "=r"(r[1]), "=r"(r[2]), "=r"(r[3]) : "r"(addr));
}
__device__ __forceinline__ void mma_f16(float* d, const uint32_t* a, const uint32_t* b) {
    asm volatile("mma.sync.aligned.m16n8k16.row.col.f32.f16.f16.f32 "
        "{%0,%1,%2,%3}, {%4,%5,%6,%7}, {%8,%9}, {%0,%1,%2,%3};"
        : "+f"(d[0]), "+f"(d[1]), "+f"(d[2]), "+f"(d[3])
        : "r"(a[0]), "r"(a[1]), "r"(a[2]), "r"(a[3]), "r"(b[0]), "r"(b[1]));
}
#define CP16(dst, src) asm volatile("cp.async.cg.shared.global [%0], [%1], 16;" :: "r"(dst), "l"(src))
#define CP_COMMIT() asm volatile("cp.async.commit_group;" ::: "memory")
#define CP_WAIT0()  asm volatile("cp.async.wait_group 0;" ::: "memory")
#define CP_WAIT1()  asm volatile("cp.async.wait_group 1;" ::: "memory")

// ============================================================
// prep: W -> fp16 hi/lo split
// ============================================================
__global__ void __launch_bounds__(256) prep_w_kernel(const float* __restrict__ Wk,
                                                     const float* __restrict__ We)
{
    int t = blockIdx.x * 256 + threadIdx.x;   // 65536 total
    float a = Wk[t];
    __half h = __float2half_rn(a);
    g_wk2[t] = h;
    g_wk2[65536 + t] = __float2half_rn(a - __half2float(h));
    float b = We[t];
    h = __float2half_rn(b);
    g_we2[t] = h;
    g_we2[65536 + t] = __float2half_rn(b - __half2float(h));
}

// ============================================================
// prep: edge fp32 -> g_a16 fp16 (8 elems/thread, streaming)
// ============================================================
__global__ void __launch_bounds__(256) prep_a16_kernel(const float* __restrict__ E)
{
    size_t e0 = ((size_t)blockIdx.x * 256 + threadIdx.x) * 8;
    float4 f0 = *(const float4*)(E + e0);
    float4 f1 = *(const float4*)(E + e0 + 4);
    union { __half2 h[4]; uint4 u; } o;
    o.h[0] = __floats2half2_rn(f0.x, f0.y);
    o.h[1] = __floats2half2_rn(f0.z, f0.w);
    o.h[2] = __floats2half2_rn(f1.x, f1.y);
    o.h[3] = __floats2half2_rn(f1.z, f1.w);
    *(uint4*)(g_a16 + e0) = o.u;
}

// ============================================================
// prep: (msg ⊙ k) fp32 -> g_a16 fp16
// ============================================================
__global__ void __launch_bounds__(256) prep_k2_kernel()
{
    size_t e0 = ((size_t)blockIdx.x * 256 + threadIdx.x) * 8;
    int r = (int)(e0 >> 8);
    int c = (int)(e0 & 255);           // multiple of 8, within one head block
    int b = r >> 14, m = (r >> 7) & 127, n = r & 127;
    float s = g_msg[(((b << 3) + (c >> 5)) << 14) + (m << 7) + n];
    float4 f0 = *(const float4*)(g_k + e0);
    float4 f1 = *(const float4*)(g_k + e0 + 4);
    union { __half2 h[4]; uint4 u; } o;
    o.h[0] = __floats2half2_rn(f0.x * s, f0.y * s);
    o.h[1] = __floats2half2_rn(f0.z * s, f0.w * s);
    o.h[2] = __floats2half2_rn(f1.x * s, f1.y * s);
    o.h[3] = __floats2half2_rn(f1.z * s, f1.w * s);
    *(uint4*)(g_a16 + e0) = o.u;
}

// ============================================================
// fp16 tensor GEMM: C[131072,256] = act(A @ (Whi+Wlo)^T + bias)
// BM=128 BN=128 BK=32, 8 warps, warp tile 32x64.
// smem/stage: A 10240B, Bhi 10240B, Blo 10240B (80B row stride).
// ============================================================
#define ST_A   0
#define ST_BH  10240
#define ST_BL  20480
#define ST_SZ  30720
#define TG_SMEM (2 * ST_SZ)

template<bool ACT>
__global__ void __launch_bounds__(256, 2) tgemm_kernel(
    const __half* __restrict__ A, const __half* __restrict__ W2,
    const float* __restrict__ bias, float* __restrict__ C)
{
    extern __shared__ char smem[];
    const uint32_t sb = smem_u32(smem);
    const int tid = threadIdx.x;
    const int wid = tid >> 5, lane = tid & 31;
    const int wm = wid >> 1, wn = wid & 1;
    const int col0 = blockIdx.x * 128;
    const int r0 = blockIdx.y * 128;

    float acc[2][8][4];
    #pragma unroll
    for (int i = 0; i < 2; i++)
        #pragma unroll
        for (int j = 0; j < 8; j++)
            #pragma unroll
            for (int q = 0; q < 4; q++) acc[i][j][q] = 0.f;

    const uint32_t aA = sb + (wm * 32 + (lane & 15)) * 80 + (lane >> 4) * 16;
    const uint32_t bA = sb + ST_BH +
        (wn * 64 + ((lane >> 4) & 1) * 8 + (lane & 7)) * 80 + ((lane >> 3) & 1) * 16;

    auto fill = [&](int c, int stg) {
        uint32_t base = sb + stg * ST_SZ;
        #pragma unroll
        for (int u = 0; u < 2; u++) {
            int idx = tid * 2 + u;           // 512 16B chunks
            int row = idx >> 2, q = idx & 3;
            uint32_t doff = (uint32_t)(row * 80 + q * 16);
            const __half* sa = A + (((size_t)(r0 + row)) << 8) + c * 32 + q * 8;
            CP16(base + ST_A + doff, (const char*)sa);
            const __half* sh = W2 + (((size_t)(col0 + row)) << 8) + c * 32 + q * 8;
            CP16(base + ST_BH + doff, (const char*)sh);
            CP16(base + ST_BL + doff, (const char*)(sh + 65536));
        }
        CP_COMMIT();
    };

    fill(0, 0);
    #pragma unroll 1
    for (int c = 0; c < 8; c++) {
        const int stg = c & 1;
        if (c < 7) { fill(c + 1, stg ^ 1); CP_WAIT1(); }
        else CP_WAIT0();
        __syncthreads();
        const uint32_t ab = aA + stg * ST_SZ;
        const uint32_t bb = bA + stg * ST_SZ;
        #pragma unroll
        for (int ks = 0; ks < 2; ks++) {
            const uint32_t koff = ks * 32;
            uint32_t ah[8], bf[16];
            ldsm4(&ah[0], ab + koff);
            ldsm4(&ah[4], ab + 16 * 80 + koff);
            #pragma unroll
            for (int ng = 0; ng < 4; ng++)
                ldsm4(&bf[ng * 4], bb + ng * 16 * 80 + koff);
            #pragma unroll
            for (int mt = 0; mt < 2; mt++)
                #pragma unroll
                for (int nt = 0; nt < 8; nt++)
                    mma_f16(acc[mt][nt], &ah[mt * 4], &bf[(nt >> 1) * 4 + (nt & 1) * 2]);
            #pragma unroll
            for (int ng = 0; ng < 4; ng++)
                ldsm4(&bf[ng * 4], bb + (ST_BL - ST_BH) + ng * 16 * 80 + koff);
            #pragma unroll
            for (int mt = 0; mt < 2; mt++)
                #pragma unroll
                for (int nt = 0; nt < 8; nt++)
                    mma_f16(acc[mt][nt], &ah[mt * 4], &bf[(nt >> 1) * 4 + (nt & 1) * 2]);
        }
        __syncthreads();
    }

    // epilogue: bias (+mish), float2 stores
    #pragma unroll
    for (int nt = 0; nt < 8; nt++) {
        const int col = col0 + wn * 64 + nt * 8 + (lane & 3) * 2;
        const float b0 = bias[col], b1 = bias[col + 1];
        #pragma unroll
        for (int mt = 0; mt < 2; mt++) {
            int row = r0 + wm * 32 + mt * 16 + (lane >> 2);
            float v0 = acc[mt][nt][0] + b0, v1 = acc[mt][nt][1] + b1;
            float v2 = acc[mt][nt][2] + b0, v3 = acc[mt][nt][3] + b1;
            if (ACT) { v0 = mish_f(v0); v1 = mish_f(v1); v2 = mish_f(v2); v3 = mish_f(v3); }
            float2 p0; p0.x = v0; p0.y = v1;
            float2 p1; p1.x = v2; p1.y = v3;
            *(float2*)(C + (size_t)row * 256 + col) = p0;
            *(float2*)(C + (size_t)(row + 8) * 256 + col) = p1;
        }
    }
}

// ============================================================
// fp32 SGEMM core for the small (1024-row) projections
// ============================================================
template<bool ACT>
__device__ __forceinline__ void gemm_core(
    const float* __restrict__ A, const float* __restrict__ W,
    const float* __restrict__ bias, float* __restrict__ C,
    int row0, int col0)
{
    __shared__ __align__(16) float As[16][132];
    __shared__ __align__(16) float Bs[16][68];

    const int t  = threadIdx.x;
    const int tx = t & 15;
    const int ty = t >> 4;
    const int lr = t >> 2;
    const int lc = (t & 3) << 2;
    const int gr1 = row0 + lr;
    const int gr2 = gr1 + 64;

    float acc[8][4];
    #pragma unroll
    for (int i = 0; i < 8; i++)
        #pragma unroll
        for (int j = 0; j < 4; j++) acc[i][j] = 0.f;

    for (int k0 = 0; k0 < HID; k0 += 16) {
        float4 a1 = *(const float4*)(A + (size_t)gr1 * HID + k0 + lc);
        float4 a2 = *(const float4*)(A + (size_t)gr2 * HID + k0 + lc);
        As[lc + 0][lr] = a1.x; As[lc + 1][lr] = a1.y;
        As[lc + 2][lr] = a1.z; As[lc + 3][lr] = a1.w;
        As[lc + 0][lr + 64] = a2.x; As[lc + 1][lr + 64] = a2.y;
        As[lc + 2][lr + 64] = a2.z; As[lc + 3][lr + 64] = a2.w;
        float4 b4 = *(const float4*)(W + (size_t)(col0 + lr) * HID + k0 + lc);
        Bs[lc + 0][lr] = b4.x; Bs[lc + 1][lr] = b4.y;
        Bs[lc + 2][lr] = b4.z; Bs[lc + 3][lr] = b4.w;
        __syncthreads();
        #pragma unroll
        for (int kk = 0; kk < 16; kk++) {
            float4 alo = *(const float4*)&As[kk][ty * 8];
            float4 ahi = *(const float4*)&As[kk][ty * 8 + 4];
            float4 bv  = *(const float4*)&Bs[kk][tx * 4];
            float avv[8] = {alo.x, alo.y, alo.z, alo.w, ahi.x, ahi.y, ahi.z, ahi.w};
            float bw[4] = {bv.x, bv.y, bv.z, bv.w};
            #pragma unroll
            for (int i = 0; i < 8; i++)
                #pragma unroll
                for (int j = 0; j < 4; j++)
                    acc[i][j] = fmaf(avv[i], bw[j], acc[i][j]);
        }
        __syncthreads();
    }

    float4 bb = *(const float4*)(bias + col0 + tx * 4);
    float bias4[4] = {bb.x, bb.y, bb.z, bb.w};
    #pragma unroll
    for (int i = 0; i < 8; i++) {
        float v0 = acc[i][0] + bias4[0];
        float v1 = acc[i][1] + bias4[1];
        float v2 = acc[i][2] + bias4[2];
        float v3 = acc[i][3] + bias4[3];
        if (ACT) { v0 = mish_f(v0); v1 = mish_f(v1); v2 = mish_f(v2); v3 = mish_f(v3); }
        float4 o; o.x = v0; o.y = v1; o.z = v2; o.w = v3;
        *(float4*)(C + (size_t)(row0 + ty * 8 + i) * HID + col0 + tx * 4) = o;
    }
}

// merged q + v projection: gridDim (8, 8); y<4 -> q cols, y>=4 -> v cols
__global__ void __launch_bounds__(256)
gemm_qv_kernel(const float* __restrict__ node,
               const float* __restrict__ Wq, const float* __restrict__ bq,
               const float* __restrict__ Wv, const float* __restrict__ bv,
               float* __restrict__ Cq, float* __restrict__ Cv)
{
    int by = blockIdx.y;
    if (by < 4) gemm_core<false>(node, Wq, bq, Cq, blockIdx.x * 128, by * 64);
    else        gemm_core<false>(node, Wv, bv, Cv, blockIdx.x * 128, (by - 4) * 64);
}

__global__ void __launch_bounds__(256)
gemm_node_kernel(const float* __restrict__ A, const float* __restrict__ W,
                 const float* __restrict__ bias, float* __restrict__ C)
{
    gemm_core<true>(A, W, bias, C, blockIdx.x * 128, blockIdx.y * 64);
}

// ============================================================
// Scores: S[b,h,m,n] = scale * q[b,m,h].k[b,m,n,h]
// ============================================================
__global__ void __launch_bounds__(256) scores_kernel()
{
    __shared__ float qs[256];
    __shared__ __align__(16) float ks[16][260];
    const int bm = blockIdx.x;
    const int b = bm >> 7;
    const int m = bm & 127;
    const int t = threadIdx.x;

    qs[t] = g_q[bm * 256 + t];
    __syncthreads();

    const float* kbase = g_k + (size_t)bm * (128 * 256);
    const int h = t >> 4, nl = t & 15;

    for (int n0 = 0; n0 < 128; n0 += 16) {
        #pragma unroll
        for (int r = 0; r < 4; r++) {
            int idx4 = t + 256 * r;
            int nn = idx4 >> 6;
            int cc = (idx4 & 63) * 4;
            *(float4*)&ks[nn][cc] = *(const float4*)(kbase + (size_t)(n0 + nn) * 256 + cc);
        }
        __syncthreads();
        if (t < 128) {
            float acc = 0.f;
            const float* kr = &ks[nl][h * 32];
            const float* qr = &qs[h * 32];
            #pragma unroll
            for (int d = 0; d < 32; d++) acc = fmaf(qr[d], kr[d], acc);
            g_S[((size_t)(b * 8 + h) * 128 + m) * 128 + n0 + nl] = acc * QK_SCALE;
        }
        __syncthreads();
    }
}

// ============================================================
// Fused masked softmax stats + message, S tile in padded smem.
// ============================================================
#define SOFT_SMEM ((128 * 129 + 5 * 128) * 4)
__global__ void __launch_bounds__(256) softmsg_kernel(
    const float* __restrict__ dist, const float* __restrict__ mask,
    const float* __restrict__ lamp)
{
    extern __shared__ float Ss[];          // [128][129]
    float* rm  = Ss + 128 * 129;
    float* rs  = rm + 128;
    float* cm  = rs + 128;
    float* cs  = cm + 128;
    float* mks = cs + 128;
    const int bh = blockIdx.x, b = bh >> 3, t = threadIdx.x;
    const float lam = lamp[0];
    const float* Sg = g_S + (size_t)bh * 16384;

    if (t < 128) mks[t] = mask[b * 128 + t];
    #pragma unroll
    for (int rr = 0; rr < 16; rr++) {
        int idx4 = t + 256 * rr;           // 4096 float4 loads
        int i = idx4 >> 5, j = (idx4 & 31) * 4;
        float4 v = *(const float4*)(Sg + i * 128 + j);
        float* d = Ss + i * 129 + j;
        d[0] = v.x; d[1] = v.y; d[2] = v.z; d[3] = v.w;
    }
    __syncthreads();

    if (t < 128) {                         // row stats for row t
        const float* row = Ss + t * 129;
        float mx = -1e30f;
        #pragma unroll 4
        for (int j = 0; j < 128; j++) if (mks[j] != 0.f) mx = fmaxf(mx, row[j]);
        float sm = 0.f;
        #pragma unroll 4
        for (int j = 0; j < 128; j++) if (mks[j] != 0.f) sm += __expf(row[j] - mx);
        rm[t] = mx; rs[t] = 1.f / sm;
    } else {                               // column stats for col t-128
        int m = t - 128;
        float mx = -1e30f;
        #pragma unroll 4
        for (int i = 0; i < 128; i++) if (mks[i] != 0.f) mx = fmaxf(mx, Ss[i * 129 + m]);
        float sm = 0.f;
        #pragma unroll 4
        for (int i = 0; i < 128; i++) if (mks[i] != 0.f) sm += __expf(Ss[i * 129 + m] - mx);
        cm[m] = mx; cs[m] = 1.f / sm;
    }
    __syncthreads();

    const float* db = dist + (size_t)b * 16384;
    float* mb = g_msg + (size_t)bh * 16384;
    #pragma unroll 1
    for (int r = 0; r < 64; r++) {
        int idx = t + 256 * r;
        int i = idx >> 7, j = idx & 127;
        float outv = 0.f;
        if (mks[j] != 0.f) {
            float o  = __expf(Ss[i * 129 + j] - rm[i]) * rs[i];
            float in = __expf(Ss[j * 129 + i] - cm[i]) * cs[i];
            float val = (i == j) ? in : (o + in);
            outv = val * __expf(-lam * db[idx]);
        }
        mb[idx] = outv;
    }
}

// ============================================================
// node_hidden[b,m,h*32+d] = sum_n msg[b,h,m,n] * v[b,n,h*32+d]
// ============================================================
__global__ void __launch_bounds__(256) nodeh_kernel()
{
    const int bh = blockIdx.x;
    const int b = bh >> 3, h = bh & 7;
    const int t = threadIdx.x;
    __shared__ __align__(16) float vs[128 * 32];
    #pragma unroll
    for (int r = 0; r < 4; r++) {
        int idx4 = t + 256 * r;
        int n = idx4 >> 3;
        int c = (idx4 & 7) * 4;
        *(float4*)&vs[n * 32 + c] =
            *(const float4*)(g_v + (size_t)(b * 128 + n) * 256 + h * 32 + c);
    }
    __syncthreads();
    const int m = t & 127;
    const int dbase = (t >> 7) * 16;
    const float* mrow = g_msg + (size_t)bh * 16384 + m * 128;
    float acc[16];
    #pragma unroll
    for (int d = 0; d < 16; d++) acc[d] = 0.f;
    for (int n = 0; n < 128; n++) {
        float w = mrow[n];
        const float* vr = &vs[n * 32 + dbase];
        #pragma unroll
        for (int d = 0; d < 16; d++) acc[d] = fmaf(w, vr[d], acc[d]);
    }
    float* outp = g_nodeh + (size_t)(b * 128 + m) * 256 + h * 32 + dbase;
    #pragma unroll
    for (int d = 0; d < 16; d++) outp[d] = acc[d];
}

// ============================================================
extern "C" void kernel_launch(void* const* d_in, const int* in_sizes, int n_in,
                              void* d_out, int out_size)
{
    const float* node = (const float*)d_in[0];
    const float* edge = (const float*)d_in[1];
    const float* dist = (const float*)d_in[2];
    const float* mask = (const float*)d_in[3];
    const float* lam  = (const float*)d_in[4];
    const float* Wq = (const float*)d_in[5];  const float* bq = (const float*)d_in[6];
    const float* Wk = (const float*)d_in[7];  const float* bk = (const float*)d_in[8];
    const float* Wv = (const float*)d_in[9];  const float* bv = (const float*)d_in[10];
    const float* Wn = (const float*)d_in[11]; const float* bn = (const float*)d_in[12];
    const float* We = (const float*)d_in[13]; const float* be = (const float*)d_in[14];

    float* out = (float*)d_out;
    float* node_out = out;
    float* edge_out = out + (size_t)NROWS_N * HID;

    float *pk, *pq, *pv, *pnh;
    __half *pa16, *pwk2, *pwe2;
    cudaGetSymbolAddress((void**)&pk, g_k);
    cudaGetSymbolAddress((void**)&pq, g_q);
    cudaGetSymbolAddress((void**)&pv, g_v);
    cudaGetSymbolAddress((void**)&pnh, g_nodeh);
    cudaGetSymbolAddress((void**)&pa16, g_a16);
    cudaGetSymbolAddress((void**)&pwk2, g_wk2);
    cudaGetSymbolAddress((void**)&pwe2, g_we2);

    cudaFuncSetAttribute(tgemm_kernel<false>,
                         cudaFuncAttributeMaxDynamicSharedMemorySize, TG_SMEM);
    cudaFuncSetAttribute(tgemm_kernel<true>,
                         cudaFuncAttributeMaxDynamicSharedMemorySize, TG_SMEM);
    cudaFuncSetAttribute(softmsg_kernel,
                         cudaFuncAttributeMaxDynamicSharedMemorySize, SOFT_SMEM);

    dim3 gT(2, NROWS_E / 128);          // (2, 1024)

    prep_w_kernel<<<256, 256>>>(Wk, We);
    prep_a16_kernel<<<16384, 256>>>(edge);
    gemm_qv_kernel<<<dim3(8, 8), 256>>>(node, Wq, bq, Wv, bv, pq, pv);
    tgemm_kernel<false><<<gT, 256, TG_SMEM>>>(pa16, pwk2, bk, pk);
    scores_kernel<<<NROWS_N, 256>>>();
    softmsg_kernel<<<64, 256, SOFT_SMEM>>>(dist, mask, lam);
    nodeh_kernel<<<64, 256>>>();
    gemm_node_kernel<<<dim3(8, 4), 256>>>(pnh, Wn, bn, node_out);
    prep_k2_kernel<<<16384, 256>>>();
    tgemm_kernel<true><<<gT, 256, TG_SMEM>>>(pa16, pwe2, be, edge_out);
}

// round 5
// speedup vs baseline: 2.7288x; 1.2667x over previous
#include <cuda_runtime.h>
#include <cuda_fp16.h>
#include <math.h>
#include <cstdint>

#define Bb 8
#define Mm 128
#define HID 256
#define NROWS_E (Bb*Mm*Mm)   // 131072
#define NROWS_N (Bb*Mm)      // 1024
#define QK_SCALE 0.17677669529663687f  // 1/sqrt(32)

// -------- scratch (device globals) --------
__device__ __align__(16) __half g_k16[(size_t)NROWS_E * HID];  // 67 MB fp16 k
__device__ __align__(16) __half g_a16[(size_t)NROWS_E * HID];  // 67 MB fp16 A operand
__device__ float g_q[NROWS_N * HID];
__device__ float g_v[NROWS_N * HID];
__device__ float g_S[64 * 128 * 128];
__device__ float g_msg[64 * 128 * 128];
__device__ float g_nodeh[NROWS_N * HID];
__device__ __align__(16) __half g_wk16[HID * HID];
__device__ __align__(16) __half g_we16[HID * HID];

__device__ __forceinline__ float mish_f(float x) {
    if (x > 20.f) return x;
    float t = 1.f + __expf(x);
    float t2 = t * t;
    return x * __fdividef(t2 - 1.f, t2 + 1.f);
}

__device__ __forceinline__ uint32_t smem_u32(const void* p) {
    uint32_t a;
    asm("{ .reg .u64 t; cvta.to.shared.u64 t, %1; cvt.u32.u64 %0, t; }" : "=r"(a) : "l"(p));
    return a;
}
__device__ __forceinline__ void ldsm4(uint32_t* r, uint32_t addr) {
    asm volatile("ldmatrix.sync.aligned.m8n8.x4.shared.b16 {%0,%1,%2,%3}, [%4];"
        : "=r"(r[0]), "=r"(r[1]), "=r"(r[2]), "=r"(r[3]) : "r"(addr));
}
__device__ __forceinline__ void mma_f16(float* d, const uint32_t* a, const uint32_t* b) {
    asm volatile("mma.sync.aligned.m16n8k16.row.col.f32.f16.f16.f32 "
        "{%0,%1,%2,%3}, {%4,%5,%6,%7}, {%8,%9}, {%0,%1,%2,%3};"
        : "+f"(d[0]), "+f"(d[1]), "+f"(d[2]), "+f"(d[3])
        : "r"(a[0]), "r"(a[1]), "r"(a[2]), "r"(a[3]), "r"(b[0]), "r"(b[1]));
}
#define CP16(dst, src) asm volatile("cp.async.cg.shared.global [%0], [%1], 16;" :: "r"(dst), "l"(src))
#define CP_COMMIT() asm volatile("cp.async.commit_group;" ::: "memory")
#define CP_WAIT0()  asm volatile("cp.async.wait_group 0;" ::: "memory")
#define CP_WAIT1()  asm volatile("cp.async.wait_group 1;" ::: "memory")

// ============================================================
__global__ void __launch_bounds__(256) prep_w_kernel(const float* __restrict__ Wk,
                                                     const float* __restrict__ We)
{
    int t = blockIdx.x * 256 + threadIdx.x;   // 65536 total
    g_wk16[t] = __float2half_rn(Wk[t]);
    g_we16[t] = __float2half_rn(We[t]);
}

__global__ void __launch_bounds__(256) prep_a16_kernel(const float* __restrict__ E)
{
    size_t e0 = ((size_t)blockIdx.x * 256 + threadIdx.x) * 8;
    float4 f0 = *(const float4*)(E + e0);
    float4 f1 = *(const float4*)(E + e0 + 4);
    union { __half2 h[4]; uint4 u; } o;
    o.h[0] = __floats2half2_rn(f0.x, f0.y);
    o.h[1] = __floats2half2_rn(f0.z, f0.w);
    o.h[2] = __floats2half2_rn(f1.x, f1.y);
    o.h[3] = __floats2half2_rn(f1.z, f1.w);
    *(uint4*)(g_a16 + e0) = o.u;
}

// (msg ⊙ k16) -> g_a16
__global__ void __launch_bounds__(256) prep_k2_kernel()
{
    size_t e0 = ((size_t)blockIdx.x * 256 + threadIdx.x) * 8;
    int r = (int)(e0 >> 8);
    int c = (int)(e0 & 255);
    int b = r >> 14, m = (r >> 7) & 127, n = r & 127;
    float s = g_msg[(((b << 3) + (c >> 5)) << 14) + (m << 7) + n];
    union { __half2 h[4]; uint4 u; } in, o;
    in.u = *(const uint4*)(g_k16 + e0);
    #pragma unroll
    for (int i = 0; i < 4; i++) {
        float2 f = __half22float2(in.h[i]);
        o.h[i] = __floats2half2_rn(f.x * s, f.y * s);
    }
    *(uint4*)(g_a16 + e0) = o.u;
}

// ============================================================
// fp16 tensor GEMM: C[131072,256] = act(A @ W^T + bias)
// BM=128 BN=128 BK=32, 8 warps, 3-stage cp.async pipeline.
// ============================================================
#define ST_A   0
#define ST_B   10240
#define ST_SZ  20480
#define TG_SMEM (3 * ST_SZ)

template<bool OUT16, bool ACT>
__global__ void __launch_bounds__(256, 2) tgemm_kernel(
    const __half* __restrict__ A, const __half* __restrict__ W,
    const float* __restrict__ bias, void* __restrict__ Cv)
{
    extern __shared__ char smem[];
    const uint32_t sb = smem_u32(smem);
    const int tid = threadIdx.x;
    const int wid = tid >> 5, lane = tid & 31;
    const int wm = wid >> 1, wn = wid & 1;
    const int col0 = blockIdx.x * 128;
    const int r0 = blockIdx.y * 128;

    float acc[2][8][4];
    #pragma unroll
    for (int i = 0; i < 2; i++)
        #pragma unroll
        for (int j = 0; j < 8; j++)
            #pragma unroll
            for (int q = 0; q < 4; q++) acc[i][j][q] = 0.f;

    const uint32_t aA = sb + (wm * 32 + (lane & 15)) * 80 + (lane >> 4) * 16;
    const uint32_t bA = sb + ST_B +
        (wn * 64 + ((lane >> 4) & 1) * 8 + (lane & 7)) * 80 + ((lane >> 3) & 1) * 16;

    const int frow = tid >> 1, fq2 = (tid & 1) * 2;   // 2 chunks of 16B per row-half

    auto fill = [&](int c, int stg) {
        uint32_t base = sb + stg * ST_SZ;
        uint32_t doff = (uint32_t)(frow * 80 + fq2 * 16);
        const __half* sa = A + (((size_t)(r0 + frow)) << 8) + c * 32 + fq2 * 8;
        CP16(base + ST_A + doff, (const char*)sa);
        CP16(base + ST_A + doff + 16, (const char*)(sa + 8));
        const __half* sw = W + (((size_t)(col0 + frow)) << 8) + c * 32 + fq2 * 8;
        CP16(base + ST_B + doff, (const char*)sw);
        CP16(base + ST_B + doff + 16, (const char*)(sw + 8));
        CP_COMMIT();
    };

    fill(0, 0);
    fill(1, 1);
    #pragma unroll 1
    for (int c = 0; c < 8; c++) {
        if (c >= 6) CP_WAIT0(); else CP_WAIT1();
        __syncthreads();
        if (c < 6) fill(c + 2, (c + 2) % 3);
        const uint32_t soff = (uint32_t)((c % 3) * ST_SZ);
        const uint32_t ab = aA + soff;
        const uint32_t bb = bA + soff;
        #pragma unroll
        for (int ks = 0; ks < 2; ks++) {
            const uint32_t koff = ks * 32;
            uint32_t ah[8], bf[16];
            ldsm4(&ah[0], ab + koff);
            ldsm4(&ah[4], ab + 16 * 80 + koff);
            #pragma unroll
            for (int ng = 0; ng < 4; ng++)
                ldsm4(&bf[ng * 4], bb + ng * 16 * 80 + koff);
            #pragma unroll
            for (int mt = 0; mt < 2; mt++)
                #pragma unroll
                for (int nt = 0; nt < 8; nt++)
                    mma_f16(acc[mt][nt], &ah[mt * 4], &bf[(nt >> 1) * 4 + (nt & 1) * 2]);
        }
        __syncthreads();
    }

    // epilogue
    #pragma unroll
    for (int nt = 0; nt < 8; nt++) {
        const int col = col0 + wn * 64 + nt * 8 + (lane & 3) * 2;
        const float b0 = bias[col], b1 = bias[col + 1];
        #pragma unroll
        for (int mt = 0; mt < 2; mt++) {
            int row = r0 + wm * 32 + mt * 16 + (lane >> 2);
            float v0 = acc[mt][nt][0] + b0, v1 = acc[mt][nt][1] + b1;
            float v2 = acc[mt][nt][2] + b0, v3 = acc[mt][nt][3] + b1;
            if (ACT) { v0 = mish_f(v0); v1 = mish_f(v1); v2 = mish_f(v2); v3 = mish_f(v3); }
            if (OUT16) {
                __half* C = (__half*)Cv;
                *(__half2*)(C + (size_t)row * 256 + col) = __floats2half2_rn(v0, v1);
                *(__half2*)(C + (size_t)(row + 8) * 256 + col) = __floats2half2_rn(v2, v3);
            } else {
                float* C = (float*)Cv;
                float2 p0; p0.x = v0; p0.y = v1;
                float2 p1; p1.x = v2; p1.y = v3;
                *(float2*)(C + (size_t)row * 256 + col) = p0;
                *(float2*)(C + (size_t)(row + 8) * 256 + col) = p1;
            }
        }
    }
}

// ============================================================
// fp32 SGEMM core for the small (1024-row) projections
// ============================================================
template<bool ACT>
__device__ __forceinline__ void gemm_core(
    const float* __restrict__ A, const float* __restrict__ W,
    const float* __restrict__ bias, float* __restrict__ C,
    int row0, int col0)
{
    __shared__ __align__(16) float As[16][132];
    __shared__ __align__(16) float Bs[16][68];

    const int t  = threadIdx.x;
    const int tx = t & 15;
    const int ty = t >> 4;
    const int lr = t >> 2;
    const int lc = (t & 3) << 2;
    const int gr1 = row0 + lr;
    const int gr2 = gr1 + 64;

    float acc[8][4];
    #pragma unroll
    for (int i = 0; i < 8; i++)
        #pragma unroll
        for (int j = 0; j < 4; j++) acc[i][j] = 0.f;

    for (int k0 = 0; k0 < HID; k0 += 16) {
        float4 a1 = *(const float4*)(A + (size_t)gr1 * HID + k0 + lc);
        float4 a2 = *(const float4*)(A + (size_t)gr2 * HID + k0 + lc);
        As[lc + 0][lr] = a1.x; As[lc + 1][lr] = a1.y;
        As[lc + 2][lr] = a1.z; As[lc + 3][lr] = a1.w;
        As[lc + 0][lr + 64] = a2.x; As[lc + 1][lr + 64] = a2.y;
        As[lc + 2][lr + 64] = a2.z; As[lc + 3][lr + 64] = a2.w;
        float4 b4 = *(const float4*)(W + (size_t)(col0 + lr) * HID + k0 + lc);
        Bs[lc + 0][lr] = b4.x; Bs[lc + 1][lr] = b4.y;
        Bs[lc + 2][lr] = b4.z; Bs[lc + 3][lr] = b4.w;
        __syncthreads();
        #pragma unroll
        for (int kk = 0; kk < 16; kk++) {
            float4 alo = *(const float4*)&As[kk][ty * 8];
            float4 ahi = *(const float4*)&As[kk][ty * 8 + 4];
            float4 bv  = *(const float4*)&Bs[kk][tx * 4];
            float avv[8] = {alo.x, alo.y, alo.z, alo.w, ahi.x, ahi.y, ahi.z, ahi.w};
            float bw[4] = {bv.x, bv.y, bv.z, bv.w};
            #pragma unroll
            for (int i = 0; i < 8; i++)
                #pragma unroll
                for (int j = 0; j < 4; j++)
                    acc[i][j] = fmaf(avv[i], bw[j], acc[i][j]);
        }
        __syncthreads();
    }

    float4 bb = *(const float4*)(bias + col0 + tx * 4);
    float bias4[4] = {bb.x, bb.y, bb.z, bb.w};
    #pragma unroll
    for (int i = 0; i < 8; i++) {
        float v0 = acc[i][0] + bias4[0];
        float v1 = acc[i][1] + bias4[1];
        float v2 = acc[i][2] + bias4[2];
        float v3 = acc[i][3] + bias4[3];
        if (ACT) { v0 = mish_f(v0); v1 = mish_f(v1); v2 = mish_f(v2); v3 = mish_f(v3); }
        float4 o; o.x = v0; o.y = v1; o.z = v2; o.w = v3;
        *(float4*)(C + (size_t)(row0 + ty * 8 + i) * HID + col0 + tx * 4) = o;
    }
}

__global__ void __launch_bounds__(256)
gemm_qv_kernel(const float* __restrict__ node,
               const float* __restrict__ Wq, const float* __restrict__ bq,
               const float* __restrict__ Wv, const float* __restrict__ bv,
               float* __restrict__ Cq, float* __restrict__ Cv)
{
    int by = blockIdx.y;
    if (by < 4) gemm_core<false>(node, Wq, bq, Cq, blockIdx.x * 128, by * 64);
    else        gemm_core<false>(node, Wv, bv, Cv, blockIdx.x * 128, (by - 4) * 64);
}

__global__ void __launch_bounds__(256)
gemm_node_kernel(const float* __restrict__ A, const float* __restrict__ W,
                 const float* __restrict__ bias, float* __restrict__ C)
{
    gemm_core<true>(A, W, bias, C, blockIdx.x * 128, blockIdx.y * 64);
}

// ============================================================
// Scores: S[b,h,m,n] = scale * q[b,m,h].k16[b,m,n,h]
// ============================================================
__global__ void __launch_bounds__(256) scores_kernel()
{
    __shared__ float qs[256];
    __shared__ __align__(16) __half ks[16][264];
    const int bm = blockIdx.x;
    const int b = bm >> 7;
    const int m = bm & 127;
    const int t = threadIdx.x;

    qs[t] = g_q[bm * 256 + t];
    __syncthreads();

    const __half* kbase = g_k16 + (size_t)bm * (128 * 256);
    const int h = t >> 4, nl = t & 15;

    for (int n0 = 0; n0 < 128; n0 += 16) {
        #pragma unroll
        for (int r = 0; r < 2; r++) {
            int idx8 = t + 256 * r;           // 512 uint4 (8 halves each)
            int nn = idx8 >> 5;               // 32 uint4 per row
            int cc = (idx8 & 31) * 8;
            *(uint4*)&ks[nn][cc] = *(const uint4*)(kbase + (size_t)(n0 + nn) * 256 + cc);
        }
        __syncthreads();
        if (t < 128) {
            float acc = 0.f;
            const __half2* kr = (const __half2*)&ks[nl][h * 32];
            const float* qr = &qs[h * 32];
            #pragma unroll
            for (int d = 0; d < 16; d++) {
                float2 kf = __half22float2(kr[d]);
                acc = fmaf(qr[2 * d], kf.x, acc);
                acc = fmaf(qr[2 * d + 1], kf.y, acc);
            }
            g_S[((size_t)(b * 8 + h) * 128 + m) * 128 + n0 + nl] = acc * QK_SCALE;
        }
        __syncthreads();
    }
}

// ============================================================
// Fused masked softmax stats + message
// ============================================================
#define SOFT_SMEM ((128 * 129 + 5 * 128) * 4)
__global__ void __launch_bounds__(256) softmsg_kernel(
    const float* __restrict__ dist, const float* __restrict__ mask,
    const float* __restrict__ lamp)
{
    extern __shared__ float Ss[];          // [128][129]
    float* rm  = Ss + 128 * 129;
    float* rs  = rm + 128;
    float* cm  = rs + 128;
    float* cs  = cm + 128;
    float* mks = cs + 128;
    const int bh = blockIdx.x, b = bh >> 3, t = threadIdx.x;
    const float lam = lamp[0];
    const float* Sg = g_S + (size_t)bh * 16384;

    if (t < 128) mks[t] = mask[b * 128 + t];
    #pragma unroll
    for (int rr = 0; rr < 16; rr++) {
        int idx4 = t + 256 * rr;
        int i = idx4 >> 5, j = (idx4 & 31) * 4;
        float4 v = *(const float4*)(Sg + i * 128 + j);
        float* d = Ss + i * 129 + j;
        d[0] = v.x; d[1] = v.y; d[2] = v.z; d[3] = v.w;
    }
    __syncthreads();

    if (t < 128) {
        const float* row = Ss + t * 129;
        float mx = -1e30f;
        #pragma unroll 4
        for (int j = 0; j < 128; j++) if (mks[j] != 0.f) mx = fmaxf(mx, row[j]);
        float sm = 0.f;
        #pragma unroll 4
        for (int j = 0; j < 128; j++) if (mks[j] != 0.f) sm += __expf(row[j] - mx);
        rm[t] = mx; rs[t] = 1.f / sm;
    } else {
        int m = t - 128;
        float mx = -1e30f;
        #pragma unroll 4
        for (int i = 0; i < 128; i++) if (mks[i] != 0.f) mx = fmaxf(mx, Ss[i * 129 + m]);
        float sm = 0.f;
        #pragma unroll 4
        for (int i = 0; i < 128; i++) if (mks[i] != 0.f) sm += __expf(Ss[i * 129 + m] - mx);
        cm[m] = mx; cs[m] = 1.f / sm;
    }
    __syncthreads();

    const float* db = dist + (size_t)b * 16384;
    float* mb = g_msg + (size_t)bh * 16384;
    #pragma unroll 1
    for (int r = 0; r < 64; r++) {
        int idx = t + 256 * r;
        int i = idx >> 7, j = idx & 127;
        float outv = 0.f;
        if (mks[j] != 0.f) {
            float o  = __expf(Ss[i * 129 + j] - rm[i]) * rs[i];
            float in = __expf(Ss[j * 129 + i] - cm[i]) * cs[i];
            float val = (i == j) ? in : (o + in);
            outv = val * __expf(-lam * db[idx]);
        }
        mb[idx] = outv;
    }
}

// ============================================================
__global__ void __launch_bounds__(256) nodeh_kernel()
{
    const int bh = blockIdx.x;
    const int b = bh >> 3, h = bh & 7;
    const int t = threadIdx.x;
    __shared__ __align__(16) float vs[128 * 32];
    #pragma unroll
    for (int r = 0; r < 4; r++) {
        int idx4 = t + 256 * r;
        int n = idx4 >> 3;
        int c = (idx4 & 7) * 4;
        *(float4*)&vs[n * 32 + c] =
            *(const float4*)(g_v + (size_t)(b * 128 + n) * 256 + h * 32 + c);
    }
    __syncthreads();
    const int m = t & 127;
    const int dbase = (t >> 7) * 16;
    const float* mrow = g_msg + (size_t)bh * 16384 + m * 128;
    float acc[16];
    #pragma unroll
    for (int d = 0; d < 16; d++) acc[d] = 0.f;
    for (int n = 0; n < 128; n++) {
        float w = mrow[n];
        const float* vr = &vs[n * 32 + dbase];
        #pragma unroll
        for (int d = 0; d < 16; d++) acc[d] = fmaf(w, vr[d], acc[d]);
    }
    float* outp = g_nodeh + (size_t)(b * 128 + m) * 256 + h * 32 + dbase;
    #pragma unroll
    for (int d = 0; d < 16; d++) outp[d] = acc[d];
}

// ============================================================
extern "C" void kernel_launch(void* const* d_in, const int* in_sizes, int n_in,
                              void* d_out, int out_size)
{
    const float* node = (const float*)d_in[0];
    const float* edge = (const float*)d_in[1];
    const float* dist = (const float*)d_in[2];
    const float* mask = (const float*)d_in[3];
    const float* lam  = (const float*)d_in[4];
    const float* Wq = (const float*)d_in[5];  const float* bq = (const float*)d_in[6];
    const float* Wk = (const float*)d_in[7];  const float* bk = (const float*)d_in[8];
    const float* Wv = (const float*)d_in[9];  const float* bv = (const float*)d_in[10];
    const float* Wn = (const float*)d_in[11]; const float* bn = (const float*)d_in[12];
    const float* We = (const float*)d_in[13]; const float* be = (const float*)d_in[14];

    float* out = (float*)d_out;
    float* node_out = out;
    float* edge_out = out + (size_t)NROWS_N * HID;

    float *pq, *pv, *pnh;
    __half *pa16, *pk16, *pwk16, *pwe16;
    cudaGetSymbolAddress((void**)&pq, g_q);
    cudaGetSymbolAddress((void**)&pv, g_v);
    cudaGetSymbolAddress((void**)&pnh, g_nodeh);
    cudaGetSymbolAddress((void**)&pa16, g_a16);
    cudaGetSymbolAddress((void**)&pk16, g_k16);
    cudaGetSymbolAddress((void**)&pwk16, g_wk16);
    cudaGetSymbolAddress((void**)&pwe16, g_we16);

    cudaFuncSetAttribute(tgemm_kernel<true, false>,
                         cudaFuncAttributeMaxDynamicSharedMemorySize, TG_SMEM);
    cudaFuncSetAttribute(tgemm_kernel<false, true>,
                         cudaFuncAttributeMaxDynamicSharedMemorySize, TG_SMEM);
    cudaFuncSetAttribute(softmsg_kernel,
                         cudaFuncAttributeMaxDynamicSharedMemorySize, SOFT_SMEM);

    dim3 gT(2, NROWS_E / 128);          // (2, 1024)

    prep_w_kernel<<<256, 256>>>(Wk, We);
    prep_a16_kernel<<<16384, 256>>>(edge);
    gemm_qv_kernel<<<dim3(8, 8), 256>>>(node, Wq, bq, Wv, bv, pq, pv);
    tgemm_kernel<true, false><<<gT, 256, TG_SMEM>>>(pa16, pwk16, bk, (void*)pk16);
    scores_kernel<<<NROWS_N, 256>>>();
    softmsg_kernel<<<64, 256, SOFT_SMEM>>>(dist, mask, lam);
    nodeh_kernel<<<64, 256>>>();
    gemm_node_kernel<<<dim3(8, 4), 256>>>(pnh, Wn, bn, node_out);
    prep_k2_kernel<<<16384, 256>>>();
    tgemm_kernel<false, true><<<gT, 256, TG_SMEM>>>(pa16, pwe16, be, edge_out);
}

// round 6
// speedup vs baseline: 2.7704x; 1.0152x over previous
#include <cuda_runtime.h>
#include <cuda_fp16.h>
#include <math.h>
#include <cstdint>

#define Bb 8
#define Mm 128
#define HID 256
#define NROWS_E (Bb*Mm*Mm)   // 131072
#define NROWS_N (Bb*Mm)      // 1024
#define QK_SCALE 0.17677669529663687f  // 1/sqrt(32)

// -------- scratch (device globals) --------
__device__ __align__(16) __half g_k16[(size_t)NROWS_E * HID];  // 67 MB fp16 k
__device__ __align__(16) __half g_a16[(size_t)NROWS_E * HID];  // 67 MB fp16 A operand
__device__ float g_q[NROWS_N * HID];
__device__ float g_v[NROWS_N * HID];
__device__ float g_S[64 * 128 * 128];
__device__ float g_msg[64 * 128 * 128];
__device__ float g_nodeh[NROWS_N * HID];
__device__ __align__(16) __half g_wk16[HID * HID];
__device__ __align__(16) __half g_we16[HID * HID];

__device__ __forceinline__ float mish_f(float x) {
    if (x > 20.f) return x;
    float t = 1.f + __expf(x);
    float t2 = t * t;
    return x * __fdividef(t2 - 1.f, t2 + 1.f);
}

__device__ __forceinline__ uint32_t smem_u32(const void* p) {
    uint32_t a;
    asm("{ .reg .u64 t; cvta.to.shared.u64 t, %1; cvt.u32.u64 %0, t; }" : "=r"(a) : "l"(p));
    return a;
}
__device__ __forceinline__ void ldsm4(uint32_t* r, uint32_t addr) {
    asm volatile("ldmatrix.sync.aligned.m8n8.x4.shared.b16 {%0,%1,%2,%3}, [%4];"
        : "=r"(r[0]), "=r"(r[1]), "=r"(r[2]), "=r"(r[3]) : "r"(addr));
}
__device__ __forceinline__ void mma_f16(float* d, const uint32_t* a, const uint32_t* b) {
    asm volatile("mma.sync.aligned.m16n8k16.row.col.f32.f16.f16.f32 "
        "{%0,%1,%2,%3}, {%4,%5,%6,%7}, {%8,%9}, {%0,%1,%2,%3};"
        : "+f"(d[0]), "+f"(d[1]), "+f"(d[2]), "+f"(d[3])
        : "r"(a[0]), "r"(a[1]), "r"(a[2]), "r"(a[3]), "r"(b[0]), "r"(b[1]));
}
#define CP16(dst, src) asm volatile("cp.async.cg.shared.global [%0], [%1], 16;" :: "r"(dst), "l"(src))
#define CP_COMMIT() asm volatile("cp.async.commit_group;" ::: "memory")
#define CP_WAIT0()  asm volatile("cp.async.wait_group 0;" ::: "memory")
#define CP_WAIT1()  asm volatile("cp.async.wait_group 1;" ::: "memory")

// ============================================================
__global__ void __launch_bounds__(256) prep_w_kernel(const float* __restrict__ Wk,
                                                     const float* __restrict__ We)
{
    int t = blockIdx.x * 256 + threadIdx.x;   // 65536 total
    g_wk16[t] = __float2half_rn(Wk[t]);
    g_we16[t] = __float2half_rn(We[t]);
}

__global__ void __launch_bounds__(256) prep_a16_kernel(const float* __restrict__ E)
{
    size_t e0 = ((size_t)blockIdx.x * 256 + threadIdx.x) * 8;
    float4 f0 = *(const float4*)(E + e0);
    float4 f1 = *(const float4*)(E + e0 + 4);
    union { __half2 h[4]; uint4 u; } o;
    o.h[0] = __floats2half2_rn(f0.x, f0.y);
    o.h[1] = __floats2half2_rn(f0.z, f0.w);
    o.h[2] = __floats2half2_rn(f1.x, f1.y);
    o.h[3] = __floats2half2_rn(f1.z, f1.w);
    *(uint4*)(g_a16 + e0) = o.u;
}

// (msg ⊙ k16) -> g_a16
__global__ void __launch_bounds__(256) prep_k2_kernel()
{
    size_t e0 = ((size_t)blockIdx.x * 256 + threadIdx.x) * 8;
    int r = (int)(e0 >> 8);
    int c = (int)(e0 & 255);
    int b = r >> 14, m = (r >> 7) & 127, n = r & 127;
    float s = g_msg[(((b << 3) + (c >> 5)) << 14) + (m << 7) + n];
    union { __half2 h[4]; uint4 u; } in, o;
    in.u = *(const uint4*)(g_k16 + e0);
    #pragma unroll
    for (int i = 0; i < 4; i++) {
        float2 f = __half22float2(in.h[i]);
        o.h[i] = __floats2half2_rn(f.x * s, f.y * s);
    }
    *(uint4*)(g_a16 + e0) = o.u;
}

// ============================================================
// fp16 tensor GEMM: C[131072,256] = act(A @ W^T + bias)
// BM=64 BN=256 BK=32, 8 warps (warp tile 32x64), grid=2048.
// 3-stage cp.async pipeline, ONE __syncthreads per chunk.
// ============================================================
#define ST_A   0
#define ST_B   5120
#define ST_SZ  25600
#define TG_SMEM (3 * ST_SZ)

template<bool OUT16, bool ACT>
__global__ void __launch_bounds__(256, 2) tgemm_kernel(
    const __half* __restrict__ A, const __half* __restrict__ W,
    const float* __restrict__ bias, void* __restrict__ Cv)
{
    extern __shared__ char smem[];
    const uint32_t sb = smem_u32(smem);
    const int tid = threadIdx.x;
    const int wid = tid >> 5, lane = tid & 31;
    const int wm = wid >> 2, wn = wid & 3;      // warp tile: rows wm*32, cols wn*64
    const int r0 = blockIdx.x * 64;

    float acc[2][8][4];
    #pragma unroll
    for (int i = 0; i < 2; i++)
        #pragma unroll
        for (int j = 0; j < 8; j++)
            #pragma unroll
            for (int q = 0; q < 4; q++) acc[i][j][q] = 0.f;

    const uint32_t aA = sb + ST_A + (wm * 32 + (lane & 15)) * 80 + (lane >> 4) * 16;
    const uint32_t bA = sb + ST_B +
        (wn * 64 + ((lane >> 4) & 1) * 8 + (lane & 7)) * 80 + ((lane >> 3) & 1) * 16;

    const int arow = tid >> 2, aq = tid & 3;    // A: 64 rows x 4 chunks = 256

    auto fill = [&](int c, int stg) {
        uint32_t base = sb + stg * ST_SZ;
        // A: one 16B chunk per thread
        CP16(base + ST_A + (uint32_t)(arow * 80 + aq * 16),
             (const char*)(A + (((size_t)(r0 + arow)) << 8) + c * 32 + aq * 8));
        // B: four 16B chunks per thread (256 rows x 4)
        #pragma unroll
        for (int u = 0; u < 4; u++) {
            int idx = tid + 256 * u;
            int row = idx >> 2, q = idx & 3;
            CP16(base + ST_B + (uint32_t)(row * 80 + q * 16),
                 (const char*)(W + (((size_t)row) << 8) + c * 32 + q * 8));
        }
        CP_COMMIT();
    };

    fill(0, 0);
    fill(1, 1);
    #pragma unroll 1
    for (int c = 0; c < 8; c++) {
        if (c < 7) CP_WAIT1(); else CP_WAIT0();
        __syncthreads();
        if (c < 6) fill(c + 2, (c + 2) % 3);
        const uint32_t soff = (uint32_t)((c % 3) * ST_SZ);
        const uint32_t ab = aA + soff;
        const uint32_t bb = bA + soff;
        #pragma unroll
        for (int ks = 0; ks < 2; ks++) {
            const uint32_t koff = ks * 32;
            uint32_t ah[8], bf[16];
            ldsm4(&ah[0], ab + koff);
            ldsm4(&ah[4], ab + 16 * 80 + koff);
            #pragma unroll
            for (int ng = 0; ng < 4; ng++)
                ldsm4(&bf[ng * 4], bb + ng * 16 * 80 + koff);
            #pragma unroll
            for (int mt = 0; mt < 2; mt++)
                #pragma unroll
                for (int nt = 0; nt < 8; nt++)
                    mma_f16(acc[mt][nt], &ah[mt * 4], &bf[(nt >> 1) * 4 + (nt & 1) * 2]);
        }
    }

    // epilogue
    #pragma unroll
    for (int nt = 0; nt < 8; nt++) {
        const int col = wn * 64 + nt * 8 + (lane & 3) * 2;
        const float b0 = bias[col], b1 = bias[col + 1];
        #pragma unroll
        for (int mt = 0; mt < 2; mt++) {
            int row = r0 + wm * 32 + mt * 16 + (lane >> 2);
            float v0 = acc[mt][nt][0] + b0, v1 = acc[mt][nt][1] + b1;
            float v2 = acc[mt][nt][2] + b0, v3 = acc[mt][nt][3] + b1;
            if (ACT) { v0 = mish_f(v0); v1 = mish_f(v1); v2 = mish_f(v2); v3 = mish_f(v3); }
            if (OUT16) {
                __half* C = (__half*)Cv;
                *(__half2*)(C + (size_t)row * 256 + col) = __floats2half2_rn(v0, v1);
                *(__half2*)(C + (size_t)(row + 8) * 256 + col) = __floats2half2_rn(v2, v3);
            } else {
                float* C = (float*)Cv;
                float2 p0; p0.x = v0; p0.y = v1;
                float2 p1; p1.x = v2; p1.y = v3;
                *(float2*)(C + (size_t)row * 256 + col) = p0;
                *(float2*)(C + (size_t)(row + 8) * 256 + col) = p1;
            }
        }
    }
}

// ============================================================
// fp32 SGEMM core for the small (1024-row) projections
// ============================================================
template<bool ACT>
__device__ __forceinline__ void gemm_core(
    const float* __restrict__ A, const float* __restrict__ W,
    const float* __restrict__ bias, float* __restrict__ C,
    int row0, int col0)
{
    __shared__ __align__(16) float As[16][132];
    __shared__ __align__(16) float Bs[16][68];

    const int t  = threadIdx.x;
    const int tx = t & 15;
    const int ty = t >> 4;
    const int lr = t >> 2;
    const int lc = (t & 3) << 2;
    const int gr1 = row0 + lr;
    const int gr2 = gr1 + 64;

    float acc[8][4];
    #pragma unroll
    for (int i = 0; i < 8; i++)
        #pragma unroll
        for (int j = 0; j < 4; j++) acc[i][j] = 0.f;

    for (int k0 = 0; k0 < HID; k0 += 16) {
        float4 a1 = *(const float4*)(A + (size_t)gr1 * HID + k0 + lc);
        float4 a2 = *(const float4*)(A + (size_t)gr2 * HID + k0 + lc);
        As[lc + 0][lr] = a1.x; As[lc + 1][lr] = a1.y;
        As[lc + 2][lr] = a1.z; As[lc + 3][lr] = a1.w;
        As[lc + 0][lr + 64] = a2.x; As[lc + 1][lr + 64] = a2.y;
        As[lc + 2][lr + 64] = a2.z; As[lc + 3][lr + 64] = a2.w;
        float4 b4 = *(const float4*)(W + (size_t)(col0 + lr) * HID + k0 + lc);
        Bs[lc + 0][lr] = b4.x; Bs[lc + 1][lr] = b4.y;
        Bs[lc + 2][lr] = b4.z; Bs[lc + 3][lr] = b4.w;
        __syncthreads();
        #pragma unroll
        for (int kk = 0; kk < 16; kk++) {
            float4 alo = *(const float4*)&As[kk][ty * 8];
            float4 ahi = *(const float4*)&As[kk][ty * 8 + 4];
            float4 bv  = *(const float4*)&Bs[kk][tx * 4];
            float avv[8] = {alo.x, alo.y, alo.z, alo.w, ahi.x, ahi.y, ahi.z, ahi.w};
            float bw[4] = {bv.x, bv.y, bv.z, bv.w};
            #pragma unroll
            for (int i = 0; i < 8; i++)
                #pragma unroll
                for (int j = 0; j < 4; j++)
                    acc[i][j] = fmaf(avv[i], bw[j], acc[i][j]);
        }
        __syncthreads();
    }

    float4 bb = *(const float4*)(bias + col0 + tx * 4);
    float bias4[4] = {bb.x, bb.y, bb.z, bb.w};
    #pragma unroll
    for (int i = 0; i < 8; i++) {
        float v0 = acc[i][0] + bias4[0];
        float v1 = acc[i][1] + bias4[1];
        float v2 = acc[i][2] + bias4[2];
        float v3 = acc[i][3] + bias4[3];
        if (ACT) { v0 = mish_f(v0); v1 = mish_f(v1); v2 = mish_f(v2); v3 = mish_f(v3); }
        float4 o; o.x = v0; o.y = v1; o.z = v2; o.w = v3;
        *(float4*)(C + (size_t)(row0 + ty * 8 + i) * HID + col0 + tx * 4) = o;
    }
}

__global__ void __launch_bounds__(256)
gemm_qv_kernel(const float* __restrict__ node,
               const float* __restrict__ Wq, const float* __restrict__ bq,
               const float* __restrict__ Wv, const float* __restrict__ bv,
               float* __restrict__ Cq, float* __restrict__ Cv)
{
    int by = blockIdx.y;
    if (by < 4) gemm_core<false>(node, Wq, bq, Cq, blockIdx.x * 128, by * 64);
    else        gemm_core<false>(node, Wv, bv, Cv, blockIdx.x * 128, (by - 4) * 64);
}

__global__ void __launch_bounds__(256)
gemm_node_kernel(const float* __restrict__ A, const float* __restrict__ W,
                 const float* __restrict__ bias, float* __restrict__ C)
{
    gemm_core<true>(A, W, bias, C, blockIdx.x * 128, blockIdx.y * 64);
}

// ============================================================
// Scores: S[b,h,m,n] = scale * q[b,m,h].k16[b,m,n,h]
// ============================================================
__global__ void __launch_bounds__(256) scores_kernel()
{
    __shared__ float qs[256];
    __shared__ __align__(16) __half ks[16][264];
    const int bm = blockIdx.x;
    const int b = bm >> 7;
    const int m = bm & 127;
    const int t = threadIdx.x;

    qs[t] = g_q[bm * 256 + t];
    __syncthreads();

    const __half* kbase = g_k16 + (size_t)bm * (128 * 256);
    const int h = t >> 4, nl = t & 15;

    for (int n0 = 0; n0 < 128; n0 += 16) {
        #pragma unroll
        for (int r = 0; r < 2; r++) {
            int idx8 = t + 256 * r;
            int nn = idx8 >> 5;
            int cc = (idx8 & 31) * 8;
            *(uint4*)&ks[nn][cc] = *(const uint4*)(kbase + (size_t)(n0 + nn) * 256 + cc);
        }
        __syncthreads();
        if (t < 128) {
            float acc = 0.f;
            const __half2* kr = (const __half2*)&ks[nl][h * 32];
            const float* qr = &qs[h * 32];
            #pragma unroll
            for (int d = 0; d < 16; d++) {
                float2 kf = __half22float2(kr[d]);
                acc = fmaf(qr[2 * d], kf.x, acc);
                acc = fmaf(qr[2 * d + 1], kf.y, acc);
            }
            g_S[((size_t)(b * 8 + h) * 128 + m) * 128 + n0 + nl] = acc * QK_SCALE;
        }
        __syncthreads();
    }
}

// ============================================================
// Fused masked softmax stats + message
// ============================================================
#define SOFT_SMEM ((128 * 129 + 5 * 128) * 4)
__global__ void __launch_bounds__(256) softmsg_kernel(
    const float* __restrict__ dist, const float* __restrict__ mask,
    const float* __restrict__ lamp)
{
    extern __shared__ float Ss[];          // [128][129]
    float* rm  = Ss + 128 * 129;
    float* rs  = rm + 128;
    float* cm  = rs + 128;
    float* cs  = cm + 128;
    float* mks = cs + 128;
    const int bh = blockIdx.x, b = bh >> 3, t = threadIdx.x;
    const float lam = lamp[0];
    const float* Sg = g_S + (size_t)bh * 16384;

    if (t < 128) mks[t] = mask[b * 128 + t];
    #pragma unroll
    for (int rr = 0; rr < 16; rr++) {
        int idx4 = t + 256 * rr;
        int i = idx4 >> 5, j = (idx4 & 31) * 4;
        float4 v = *(const float4*)(Sg + i * 128 + j);
        float* d = Ss + i * 129 + j;
        d[0] = v.x; d[1] = v.y; d[2] = v.z; d[3] = v.w;
    }
    __syncthreads();

    if (t < 128) {
        const float* row = Ss + t * 129;
        float mx = -1e30f;
        #pragma unroll 4
        for (int j = 0; j < 128; j++) if (mks[j] != 0.f) mx = fmaxf(mx, row[j]);
        float sm = 0.f;
        #pragma unroll 4
        for (int j = 0; j < 128; j++) if (mks[j] != 0.f) sm += __expf(row[j] - mx);
        rm[t] = mx; rs[t] = 1.f / sm;
    } else {
        int m = t - 128;
        float mx = -1e30f;
        #pragma unroll 4
        for (int i = 0; i < 128; i++) if (mks[i] != 0.f) mx = fmaxf(mx, Ss[i * 129 + m]);
        float sm = 0.f;
        #pragma unroll 4
        for (int i = 0; i < 128; i++) if (mks[i] != 0.f) sm += __expf(Ss[i * 129 + m] - mx);
        cm[m] = mx; cs[m] = 1.f / sm;
    }
    __syncthreads();

    const float* db = dist + (size_t)b * 16384;
    float* mb = g_msg + (size_t)bh * 16384;
    #pragma unroll 1
    for (int r = 0; r < 64; r++) {
        int idx = t + 256 * r;
        int i = idx >> 7, j = idx & 127;
        float outv = 0.f;
        if (mks[j] != 0.f) {
            float o  = __expf(Ss[i * 129 + j] - rm[i]) * rs[i];
            float in = __expf(Ss[j * 129 + i] - cm[i]) * cs[i];
            float val = (i == j) ? in : (o + in);
            outv = val * __expf(-lam * db[idx]);
        }
        mb[idx] = outv;
    }
}

// ============================================================
__global__ void __launch_bounds__(256) nodeh_kernel()
{
    const int bh = blockIdx.x;
    const int b = bh >> 3, h = bh & 7;
    const int t = threadIdx.x;
    __shared__ __align__(16) float vs[128 * 32];
    #pragma unroll
    for (int r = 0; r < 4; r++) {
        int idx4 = t + 256 * r;
        int n = idx4 >> 3;
        int c = (idx4 & 7) * 4;
        *(float4*)&vs[n * 32 + c] =
            *(const float4*)(g_v + (size_t)(b * 128 + n) * 256 + h * 32 + c);
    }
    __syncthreads();
    const int m = t & 127;
    const int dbase = (t >> 7) * 16;
    const float* mrow = g_msg + (size_t)bh * 16384 + m * 128;
    float acc[16];
    #pragma unroll
    for (int d = 0; d < 16; d++) acc[d] = 0.f;
    for (int n = 0; n < 128; n++) {
        float w = mrow[n];
        const float* vr = &vs[n * 32 + dbase];
        #pragma unroll
        for (int d = 0; d < 16; d++) acc[d] = fmaf(w, vr[d], acc[d]);
    }
    float* outp = g_nodeh + (size_t)(b * 128 + m) * 256 + h * 32 + dbase;
    #pragma unroll
    for (int d = 0; d < 16; d++) outp[d] = acc[d];
}

// ============================================================
extern "C" void kernel_launch(void* const* d_in, const int* in_sizes, int n_in,
                              void* d_out, int out_size)
{
    const float* node = (const float*)d_in[0];
    const float* edge = (const float*)d_in[1];
    const float* dist = (const float*)d_in[2];
    const float* mask = (const float*)d_in[3];
    const float* lam  = (const float*)d_in[4];
    const float* Wq = (const float*)d_in[5];  const float* bq = (const float*)d_in[6];
    const float* Wk = (const float*)d_in[7];  const float* bk = (const float*)d_in[8];
    const float* Wv = (const float*)d_in[9];  const float* bv = (const float*)d_in[10];
    const float* Wn = (const float*)d_in[11]; const float* bn = (const float*)d_in[12];
    const float* We = (const float*)d_in[13]; const float* be = (const float*)d_in[14];

    float* out = (float*)d_out;
    float* node_out = out;
    float* edge_out = out + (size_t)NROWS_N * HID;

    float *pq, *pv, *pnh;
    __half *pa16, *pk16, *pwk16, *pwe16;
    cudaGetSymbolAddress((void**)&pq, g_q);
    cudaGetSymbolAddress((void**)&pv, g_v);
    cudaGetSymbolAddress((void**)&pnh, g_nodeh);
    cudaGetSymbolAddress((void**)&pa16, g_a16);
    cudaGetSymbolAddress((void**)&pk16, g_k16);
    cudaGetSymbolAddress((void**)&pwk16, g_wk16);
    cudaGetSymbolAddress((void**)&pwe16, g_we16);

    cudaFuncSetAttribute(tgemm_kernel<true, false>,
                         cudaFuncAttributeMaxDynamicSharedMemorySize, TG_SMEM);
    cudaFuncSetAttribute(tgemm_kernel<false, true>,
                         cudaFuncAttributeMaxDynamicSharedMemorySize, TG_SMEM);
    cudaFuncSetAttribute(softmsg_kernel,
                         cudaFuncAttributeMaxDynamicSharedMemorySize, SOFT_SMEM);

    prep_w_kernel<<<256, 256>>>(Wk, We);
    prep_a16_kernel<<<16384, 256>>>(edge);
    gemm_qv_kernel<<<dim3(8, 8), 256>>>(node, Wq, bq, Wv, bv, pq, pv);
    tgemm_kernel<true, false><<<2048, 256, TG_SMEM>>>(pa16, pwk16, bk, (void*)pk16);
    scores_kernel<<<NROWS_N, 256>>>();
    softmsg_kernel<<<64, 256, SOFT_SMEM>>>(dist, mask, lam);
    nodeh_kernel<<<64, 256>>>();
    gemm_node_kernel<<<dim3(8, 4), 256>>>(pnh, Wn, bn, node_out);
    prep_k2_kernel<<<16384, 256>>>();
    tgemm_kernel<false, true><<<2048, 256, TG_SMEM>>>(pa16, pwe16, be, edge_out);
}

// round 8
// speedup vs baseline: 2.9435x; 1.0625x over previous
#include <cuda_runtime.h>
#include <cuda_fp16.h>
#include <math.h>
#include <cstdint>

#define Bb 8
#define Mm 128
#define HID 256
#define NROWS_E (Bb*Mm*Mm)   // 131072
#define NROWS_N (Bb*Mm)      // 1024
#define QK_SCALE 0.17677669529663687f  // 1/sqrt(32)

// -------- scratch (device globals) --------
__device__ __align__(16) __half g_k16[(size_t)NROWS_E * HID];  // 67 MB fp16 k
__device__ __align__(16) __half g_a16[(size_t)NROWS_E * HID];  // 67 MB fp16 edge
__device__ float g_q[NROWS_N * HID];
__device__ float g_v[NROWS_N * HID];
__device__ float g_S[64 * 128 * 128];
__device__ float g_msg[64 * 128 * 128];
__device__ float g_nodeh[NROWS_N * HID];
__device__ __align__(16) __half g_wk16[HID * HID];
__device__ __align__(16) __half g_we16[HID * HID];

__device__ __forceinline__ float mish_f(float x) {
    if (x > 20.f) return x;
    float t = 1.f + __expf(x);
    float t2 = t * t;
    return x * __fdividef(t2 - 1.f, t2 + 1.f);
}

__device__ __forceinline__ uint32_t smem_u32(const void* p) {
    uint32_t a;
    asm("{ .reg .u64 t; cvta.to.shared.u64 t, %1; cvt.u32.u64 %0, t; }" : "=r"(a) : "l"(p));
    return a;
}
__device__ __forceinline__ void ldsm4(uint32_t* r, uint32_t addr) {
    asm volatile("ldmatrix.sync.aligned.m8n8.x4.shared.b16 {%0,%1,%2,%3}, [%4];"
        : "=r"(r[0]), "=r"(r[1]), "=r"(r[2]), "=r"(r[3]) : "r"(addr));
}
__device__ __forceinline__ void mma_f16(float* d, const uint32_t* a, const uint32_t* b) {
    asm volatile("mma.sync.aligned.m16n8k16.row.col.f32.f16.f16.f32 "
        "{%0,%1,%2,%3}, {%4,%5,%6,%7}, {%8,%9}, {%0,%1,%2,%3};"
        : "+f"(d[0]), "+f"(d[1]), "+f"(d[2]), "+f"(d[3])
        : "r"(a[0]), "r"(a[1]), "r"(a[2]), "r"(a[3]), "r"(b[0]), "r"(b[1]));
}
#define CP16(dst, src) asm volatile("cp.async.cg.shared.global [%0], [%1], 16;" :: "r"(dst), "l"(src))
#define CP_COMMIT() asm volatile("cp.async.commit_group;" ::: "memory")
#define CP_WAIT0()  asm volatile("cp.async.wait_group 0;" ::: "memory")
#define CP_WAIT1()  asm volatile("cp.async.wait_group 1;" ::: "memory")

// ============================================================
// prep: edge fp32 -> fp16, plus W conversions in first blocks
// ============================================================
__global__ void __launch_bounds__(256) prep_kernel(const float* __restrict__ E,
                                                   const float* __restrict__ Wk,
                                                   const float* __restrict__ We)
{
    size_t e0 = ((size_t)blockIdx.x * 256 + threadIdx.x) * 8;
    float4 f0 = *(const float4*)(E + e0);
    float4 f1 = *(const float4*)(E + e0 + 4);
    union { __half2 h[4]; uint4 u; } o;
    o.h[0] = __floats2half2_rn(f0.x, f0.y);
    o.h[1] = __floats2half2_rn(f0.z, f0.w);
    o.h[2] = __floats2half2_rn(f1.x, f1.y);
    o.h[3] = __floats2half2_rn(f1.z, f1.w);
    *(uint4*)(g_a16 + e0) = o.u;
    if (blockIdx.x < 256) {
        int t = blockIdx.x * 256 + threadIdx.x;    // 65536 W elements
        g_wk16[t] = __float2half_rn(Wk[t]);
        g_we16[t] = __float2half_rn(We[t]);
    }
}

// ============================================================
// fp16 tensor GEMM: C[131072,256] = act(A' @ W^T + bias)
// A' = A (MSG: scaled per (row, head=chunk) by g_msg, fused).
// BM=64 BN=128 BK=32, 8 warps (warp tile 32x32), 3 CTAs/SM.
// 3-stage cp.async pipeline, one __syncthreads per chunk.
// ============================================================
#define ST_A    0
#define ST_B    5120
#define ST_MSG  15360
#define ST_SZ   15872
#define TG_SMEM (3 * ST_SZ)

template<bool MSG, bool OUT16, bool ACT>
__global__ void __launch_bounds__(256, 3) tgemm_kernel(
    const __half* __restrict__ A, const __half* __restrict__ W,
    const float* __restrict__ bias, void* __restrict__ Cv)
{
    extern __shared__ char smem[];
    const uint32_t sb = smem_u32(smem);
    const int tid = threadIdx.x;
    const int wid = tid >> 5, lane = tid & 31;
    const int wm = wid >> 2, wn = wid & 3;      // warp tile rows wm*32, cols wn*32
    const int col0 = blockIdx.x * 128;
    const int r0 = blockIdx.y * 64;

    int mb_base = 0;
    if (MSG) {
        int b = r0 >> 14, m = (r0 >> 7) & 127, n0 = r0 & 127;
        mb_base = b * 131072 + m * 128 + n0;    // + c*16384 per chunk
    }

    float acc[2][4][4];
    #pragma unroll
    for (int i = 0; i < 2; i++)
        #pragma unroll
        for (int j = 0; j < 4; j++)
            #pragma unroll
            for (int q = 0; q < 4; q++) acc[i][j][q] = 0.f;

    const uint32_t aA = sb + ST_A + (wm * 32 + (lane & 15)) * 80 + (lane >> 4) * 16;
    const uint32_t bA = sb + ST_B +
        (wn * 32 + ((lane >> 4) & 1) * 8 + (lane & 7)) * 80 + ((lane >> 3) & 1) * 16;

    const int arow = tid >> 2, aq = tid & 3;    // A: 64 rows x 4 chunks

    auto fill = [&](int c, int stg) {
        uint32_t base = sb + stg * ST_SZ;
        CP16(base + ST_A + (uint32_t)(arow * 80 + aq * 16),
             (const char*)(A + (((size_t)(r0 + arow)) << 8) + c * 32 + aq * 8));
        #pragma unroll
        for (int u = 0; u < 2; u++) {
            int idx = tid + 256 * u;            // B: 128 rows x 4 chunks = 512
            int row = idx >> 2, q = idx & 3;
            CP16(base + ST_B + (uint32_t)(row * 80 + q * 16),
                 (const char*)(W + (((size_t)(col0 + row)) << 8) + c * 32 + q * 8));
        }
        if (MSG && tid < 16)
            CP16(base + ST_MSG + (uint32_t)(tid * 16),
                 (const char*)(g_msg + mb_base + c * 16384 + tid * 4));
        CP_COMMIT();
    };

    fill(0, 0);
    fill(1, 1);
    #pragma unroll 1
    for (int c = 0; c < 8; c++) {
        if (c < 7) CP_WAIT1(); else CP_WAIT0();
        __syncthreads();
        if (c < 6) fill(c + 2, (c + 2) % 3);
        const uint32_t soff = (uint32_t)((c % 3) * ST_SZ);

        // msg scales for this chunk (head == c).
        // mma m16n8k16 A-fragment: regs {a0,a2} hold row g=lane>>2,
        // regs {a1,a3} hold row g+8 (within each 16-row tile).
        __half2 s00, s01, s10, s11;
        if (MSG) {
            const float* sp = (const float*)(smem + (c % 3) * ST_SZ + ST_MSG);
            int g = lane >> 2;
            s00 = __half2half2(__float2half_rn(sp[wm * 32 + g]));        // tile0 row g
            s01 = __half2half2(__float2half_rn(sp[wm * 32 + g + 8]));    // tile0 row g+8
            s10 = __half2half2(__float2half_rn(sp[wm * 32 + 16 + g]));   // tile1 row g
            s11 = __half2half2(__float2half_rn(sp[wm * 32 + 16 + g + 8]));
        }

        const uint32_t ab = aA + soff;
        const uint32_t bb = bA + soff;
        #pragma unroll
        for (int ks = 0; ks < 2; ks++) {
            const uint32_t koff = ks * 32;
            uint32_t ah[8], bf[8];
            ldsm4(&ah[0], ab + koff);
            ldsm4(&ah[4], ab + 16 * 80 + koff);
            ldsm4(&bf[0], bb + koff);
            ldsm4(&bf[4], bb + 16 * 80 + koff);
            if (MSG) {
                __half2* h = reinterpret_cast<__half2*>(ah);
                h[0] = __hmul2(h[0], s00); h[2] = __hmul2(h[2], s00);
                h[1] = __hmul2(h[1], s01); h[3] = __hmul2(h[3], s01);
                h[4] = __hmul2(h[4], s10); h[6] = __hmul2(h[6], s10);
                h[5] = __hmul2(h[5], s11); h[7] = __hmul2(h[7], s11);
            }
            #pragma unroll
            for (int mt = 0; mt < 2; mt++)
                #pragma unroll
                for (int nt = 0; nt < 4; nt++)
                    mma_f16(acc[mt][nt], &ah[mt * 4], &bf[(nt >> 1) * 4 + (nt & 1) * 2]);
        }
    }

    // epilogue
    #pragma unroll
    for (int nt = 0; nt < 4; nt++) {
        const int col = col0 + wn * 32 + nt * 8 + (lane & 3) * 2;
        const float b0 = bias[col], b1 = bias[col + 1];
        #pragma unroll
        for (int mt = 0; mt < 2; mt++) {
            int row = r0 + wm * 32 + mt * 16 + (lane >> 2);
            float v0 = acc[mt][nt][0] + b0, v1 = acc[mt][nt][1] + b1;
            float v2 = acc[mt][nt][2] + b0, v3 = acc[mt][nt][3] + b1;
            if (ACT) { v0 = mish_f(v0); v1 = mish_f(v1); v2 = mish_f(v2); v3 = mish_f(v3); }
            if (OUT16) {
                __half* C = (__half*)Cv;
                *(__half2*)(C + (size_t)row * 256 + col) = __floats2half2_rn(v0, v1);
                *(__half2*)(C + (size_t)(row + 8) * 256 + col) = __floats2half2_rn(v2, v3);
            } else {
                float* C = (float*)Cv;
                float2 p0; p0.x = v0; p0.y = v1;
                float2 p1; p1.x = v2; p1.y = v3;
                *(float2*)(C + (size_t)row * 256 + col) = p0;
                *(float2*)(C + (size_t)(row + 8) * 256 + col) = p1;
            }
        }
    }
}

// ============================================================
// fp32 SGEMM core for the small (1024-row) projections
// ============================================================
template<bool ACT>
__device__ __forceinline__ void gemm_core(
    const float* __restrict__ A, const float* __restrict__ W,
    const float* __restrict__ bias, float* __restrict__ C,
    int row0, int col0)
{
    __shared__ __align__(16) float As[16][132];
    __shared__ __align__(16) float Bs[16][68];

    const int t  = threadIdx.x;
    const int tx = t & 15;
    const int ty = t >> 4;
    const int lr = t >> 2;
    const int lc = (t & 3) << 2;
    const int gr1 = row0 + lr;
    const int gr2 = gr1 + 64;

    float acc[8][4];
    #pragma unroll
    for (int i = 0; i < 8; i++)
        #pragma unroll
        for (int j = 0; j < 4; j++) acc[i][j] = 0.f;

    for (int k0 = 0; k0 < HID; k0 += 16) {
        float4 a1 = *(const float4*)(A + (size_t)gr1 * HID + k0 + lc);
        float4 a2 = *(const float4*)(A + (size_t)gr2 * HID + k0 + lc);
        As[lc + 0][lr] = a1.x; As[lc + 1][lr] = a1.y;
        As[lc + 2][lr] = a1.z; As[lc + 3][lr] = a1.w;
        As[lc + 0][lr + 64] = a2.x; As[lc + 1][lr + 64] = a2.y;
        As[lc + 2][lr + 64] = a2.z; As[lc + 3][lr + 64] = a2.w;
        float4 b4 = *(const float4*)(W + (size_t)(col0 + lr) * HID + k0 + lc);
        Bs[lc + 0][lr] = b4.x; Bs[lc + 1][lr] = b4.y;
        Bs[lc + 2][lr] = b4.z; Bs[lc + 3][lr] = b4.w;
        __syncthreads();
        #pragma unroll
        for (int kk = 0; kk < 16; kk++) {
            float4 alo = *(const float4*)&As[kk][ty * 8];
            float4 ahi = *(const float4*)&As[kk][ty * 8 + 4];
            float4 bv  = *(const float4*)&Bs[kk][tx * 4];
            float avv[8] = {alo.x, alo.y, alo.z, alo.w, ahi.x, ahi.y, ahi.z, ahi.w};
            float bw[4] = {bv.x, bv.y, bv.z, bv.w};
            #pragma unroll
            for (int i = 0; i < 8; i++)
                #pragma unroll
                for (int j = 0; j < 4; j++)
                    acc[i][j] = fmaf(avv[i], bw[j], acc[i][j]);
        }
        __syncthreads();
    }

    float4 bb = *(const float4*)(bias + col0 + tx * 4);
    float bias4[4] = {bb.x, bb.y, bb.z, bb.w};
    #pragma unroll
    for (int i = 0; i < 8; i++) {
        float v0 = acc[i][0] + bias4[0];
        float v1 = acc[i][1] + bias4[1];
        float v2 = acc[i][2] + bias4[2];
        float v3 = acc[i][3] + bias4[3];
        if (ACT) { v0 = mish_f(v0); v1 = mish_f(v1); v2 = mish_f(v2); v3 = mish_f(v3); }
        float4 o; o.x = v0; o.y = v1; o.z = v2; o.w = v3;
        *(float4*)(C + (size_t)(row0 + ty * 8 + i) * HID + col0 + tx * 4) = o;
    }
}

__global__ void __launch_bounds__(256)
gemm_qv_kernel(const float* __restrict__ node,
               const float* __restrict__ Wq, const float* __restrict__ bq,
               const float* __restrict__ Wv, const float* __restrict__ bv,
               float* __restrict__ Cq, float* __restrict__ Cv)
{
    int by = blockIdx.y;
    if (by < 4) gemm_core<false>(node, Wq, bq, Cq, blockIdx.x * 128, by * 64);
    else        gemm_core<false>(node, Wv, bv, Cv, blockIdx.x * 128, (by - 4) * 64);
}

__global__ void __launch_bounds__(256)
gemm_node_kernel(const float* __restrict__ A, const float* __restrict__ W,
                 const float* __restrict__ bias, float* __restrict__ C)
{
    gemm_core<true>(A, W, bias, C, blockIdx.x * 128, blockIdx.y * 64);
}

// ============================================================
// Scores: S[b,h,m,n] = scale * q[b,m,h].k16[b,m,n,h]
// ============================================================
__global__ void __launch_bounds__(256) scores_kernel()
{
    __shared__ float qs[256];
    __shared__ __align__(16) __half ks[16][264];
    const int bm = blockIdx.x;
    const int b = bm >> 7;
    const int m = bm & 127;
    const int t = threadIdx.x;

    qs[t] = g_q[bm * 256 + t];
    __syncthreads();

    const __half* kbase = g_k16 + (size_t)bm * (128 * 256);
    const int h = t >> 4, nl = t & 15;

    for (int n0 = 0; n0 < 128; n0 += 16) {
        #pragma unroll
        for (int r = 0; r < 2; r++) {
            int idx8 = t + 256 * r;
            int nn = idx8 >> 5;
            int cc = (idx8 & 31) * 8;
            *(uint4*)&ks[nn][cc] = *(const uint4*)(kbase + (size_t)(n0 + nn) * 256 + cc);
        }
        __syncthreads();
        if (t < 128) {
            float acc = 0.f;
            const __half2* kr = (const __half2*)&ks[nl][h * 32];
            const float* qr = &qs[h * 32];
            #pragma unroll
            for (int d = 0; d < 16; d++) {
                float2 kf = __half22float2(kr[d]);
                acc = fmaf(qr[2 * d], kf.x, acc);
                acc = fmaf(qr[2 * d + 1], kf.y, acc);
            }
            g_S[((size_t)(b * 8 + h) * 128 + m) * 128 + n0 + nl] = acc * QK_SCALE;
        }
        __syncthreads();
    }
}

// ============================================================
// Fused masked softmax stats + message
// ============================================================
#define SOFT_SMEM ((128 * 129 + 5 * 128) * 4)
__global__ void __launch_bounds__(256) softmsg_kernel(
    const float* __restrict__ dist, const float* __restrict__ mask,
    const float* __restrict__ lamp)
{
    extern __shared__ float Ss[];          // [128][129]
    float* rm  = Ss + 128 * 129;
    float* rs  = rm + 128;
    float* cm  = rs + 128;
    float* cs  = cm + 128;
    float* mks = cs + 128;
    const int bh = blockIdx.x, b = bh >> 3, t = threadIdx.x;
    const float lam = lamp[0];
    const float* Sg = g_S + (size_t)bh * 16384;

    if (t < 128) mks[t] = mask[b * 128 + t];
    #pragma unroll
    for (int rr = 0; rr < 16; rr++) {
        int idx4 = t + 256 * rr;
        int i = idx4 >> 5, j = (idx4 & 31) * 4;
        float4 v = *(const float4*)(Sg + i * 128 + j);
        float* d = Ss + i * 129 + j;
        d[0] = v.x; d[1] = v.y; d[2] = v.z; d[3] = v.w;
    }
    __syncthreads();

    if (t < 128) {
        const float* row = Ss + t * 129;
        float mx = -1e30f;
        #pragma unroll 4
        for (int j = 0; j < 128; j++) if (mks[j] != 0.f) mx = fmaxf(mx, row[j]);
        float sm = 0.f;
        #pragma unroll 4
        for (int j = 0; j < 128; j++) if (mks[j] != 0.f) sm += __expf(row[j] - mx);
        rm[t] = mx; rs[t] = 1.f / sm;
    } else {
        int m = t - 128;
        float mx = -1e30f;
        #pragma unroll 4
        for (int i = 0; i < 128; i++) if (mks[i] != 0.f) mx = fmaxf(mx, Ss[i * 129 + m]);
        float sm = 0.f;
        #pragma unroll 4
        for (int i = 0; i < 128; i++) if (mks[i] != 0.f) sm += __expf(Ss[i * 129 + m] - mx);
        cm[m] = mx; cs[m] = 1.f / sm;
    }
    __syncthreads();

    const float* db = dist + (size_t)b * 16384;
    float* mb = g_msg + (size_t)bh * 16384;
    #pragma unroll 1
    for (int r = 0; r < 64; r++) {
        int idx = t + 256 * r;
        int i = idx >> 7, j = idx & 127;
        float outv = 0.f;
        if (mks[j] != 0.f) {
            float o  = __expf(Ss[i * 129 + j] - rm[i]) * rs[i];
            float in = __expf(Ss[j * 129 + i] - cm[i]) * cs[i];
            float val = (i == j) ? in : (o + in);
            outv = val * __expf(-lam * db[idx]);
        }
        mb[idx] = outv;
    }
}

// ============================================================
__global__ void __launch_bounds__(256) nodeh_kernel()
{
    const int bh = blockIdx.x;
    const int b = bh >> 3, h = bh & 7;
    const int t = threadIdx.x;
    __shared__ __align__(16) float vs[128 * 32];
    #pragma unroll
    for (int r = 0; r < 4; r++) {
        int idx4 = t + 256 * r;
        int n = idx4 >> 3;
        int c = (idx4 & 7) * 4;
        *(float4*)&vs[n * 32 + c] =
            *(const float4*)(g_v + (size_t)(b * 128 + n) * 256 + h * 32 + c);
    }
    __syncthreads();
    const int m = t & 127;
    const int dbase = (t >> 7) * 16;
    const float* mrow = g_msg + (size_t)bh * 16384 + m * 128;
    float acc[16];
    #pragma unroll
    for (int d = 0; d < 16; d++) acc[d] = 0.f;
    for (int n = 0; n < 128; n++) {
        float w = mrow[n];
        const float* vr = &vs[n * 32 + dbase];
        #pragma unroll
        for (int d = 0; d < 16; d++) acc[d] = fmaf(w, vr[d], acc[d]);
    }
    float* outp = g_nodeh + (size_t)(b * 128 + m) * 256 + h * 32 + dbase;
    #pragma unroll
    for (int d = 0; d < 16; d++) outp[d] = acc[d];
}

// ============================================================
extern "C" void kernel_launch(void* const* d_in, const int* in_sizes, int n_in,
                              void* d_out, int out_size)
{
    const float* node = (const float*)d_in[0];
    const float* edge = (const float*)d_in[1];
    const float* dist = (const float*)d_in[2];
    const float* mask = (const float*)d_in[3];
    const float* lam  = (const float*)d_in[4];
    const float* Wq = (const float*)d_in[5];  const float* bq = (const float*)d_in[6];
    const float* Wk = (const float*)d_in[7];  const float* bk = (const float*)d_in[8];
    const float* Wv = (const float*)d_in[9];  const float* bv = (const float*)d_in[10];
    const float* Wn = (const float*)d_in[11]; const float* bn = (const float*)d_in[12];
    const float* We = (const float*)d_in[13]; const float* be = (const float*)d_in[14];

    float* out = (float*)d_out;
    float* node_out = out;
    float* edge_out = out + (size_t)NROWS_N * HID;

    float *pq, *pv, *pnh;
    __half *pa16, *pk16, *pwk16, *pwe16;
    cudaGetSymbolAddress((void**)&pq, g_q);
    cudaGetSymbolAddress((void**)&pv, g_v);
    cudaGetSymbolAddress((void**)&pnh, g_nodeh);
    cudaGetSymbolAddress((void**)&pa16, g_a16);
    cudaGetSymbolAddress((void**)&pk16, g_k16);
    cudaGetSymbolAddress((void**)&pwk16, g_wk16);
    cudaGetSymbolAddress((void**)&pwe16, g_we16);

    cudaFuncSetAttribute((const void*)tgemm_kernel<false, true, false>,
                         cudaFuncAttributeMaxDynamicSharedMemorySize, TG_SMEM);
    cudaFuncSetAttribute((const void*)tgemm_kernel<true, false, true>,
                         cudaFuncAttributeMaxDynamicSharedMemorySize, TG_SMEM);
    cudaFuncSetAttribute((const void*)softmsg_kernel,
                         cudaFuncAttributeMaxDynamicSharedMemorySize, SOFT_SMEM);

    dim3 gT(2, NROWS_E / 64);           // (2 col blocks, 2048 row blocks)

    prep_kernel<<<16384, 256>>>(edge, Wk, We);
    gemm_qv_kernel<<<dim3(8, 8), 256>>>(node, Wq, bq, Wv, bv, pq, pv);
    tgemm_kernel<false, true, false><<<gT, 256, TG_SMEM>>>(pa16, pwk16, bk, (void*)pk16);
    scores_kernel<<<NROWS_N, 256>>>();
    softmsg_kernel<<<64, 256, SOFT_SMEM>>>(dist, mask, lam);
    tgemm_kernel<true, false, true><<<gT, 256, TG_SMEM>>>(pk16, pwe16, be, edge_out);
    nodeh_kernel<<<64, 256>>>();
    gemm_node_kernel<<<dim3(8, 4), 256>>>(pnh, Wn, bn, node_out);
}

// round 9
// speedup vs baseline: 3.0479x; 1.0355x over previous
#include <cuda_runtime.h>
#include <cuda_fp16.h>
#include <math.h>
#include <cstdint>

#define Bb 8
#define Mm 128
#define HID 256
#define NROWS_E (Bb*Mm*Mm)   // 131072
#define NROWS_N (Bb*Mm)      // 1024
#define QK_SCALE 0.17677669529663687f  // 1/sqrt(32)

// -------- scratch (device globals) --------
__device__ __align__(16) __half g_k16[(size_t)NROWS_E * HID];  // 67 MB fp16 k
__device__ __align__(16) __half g_a16[(size_t)NROWS_E * HID];  // 67 MB fp16 edge
__device__ float g_q[NROWS_N * HID];
__device__ float g_v[NROWS_N * HID];
__device__ float g_S[64 * 128 * 128];
__device__ float g_msg[64 * 128 * 128];
__device__ float g_nodeh[NROWS_N * HID];
__device__ __align__(16) __half g_wk16[HID * HID];
__device__ __align__(16) __half g_we16[HID * HID];

__device__ __forceinline__ float mish_f(float x) {
    if (x > 20.f) return x;
    float t = 1.f + __expf(x);
    float t2 = t * t;
    return x * __fdividef(t2 - 1.f, t2 + 1.f);
}

__device__ __forceinline__ uint32_t smem_u32(const void* p) {
    uint32_t a;
    asm("{ .reg .u64 t; cvta.to.shared.u64 t, %1; cvt.u32.u64 %0, t; }" : "=r"(a) : "l"(p));
    return a;
}
__device__ __forceinline__ void ldsm4(uint32_t* r, uint32_t addr) {
    asm volatile("ldmatrix.sync.aligned.m8n8.x4.shared.b16 {%0,%1,%2,%3}, [%4];"
        : "=r"(r[0]), "=r"(r[1]), "=r"(r[2]), "=r"(r[3]) : "r"(addr));
}
__device__ __forceinline__ void mma_f16(float* d, const uint32_t* a, const uint32_t* b) {
    asm volatile("mma.sync.aligned.m16n8k16.row.col.f32.f16.f16.f32 "
        "{%0,%1,%2,%3}, {%4,%5,%6,%7}, {%8,%9}, {%0,%1,%2,%3};"
        : "+f"(d[0]), "+f"(d[1]), "+f"(d[2]), "+f"(d[3])
        : "r"(a[0]), "r"(a[1]), "r"(a[2]), "r"(a[3]), "r"(b[0]), "r"(b[1]));
}
#define CP16(dst, src) asm volatile("cp.async.cg.shared.global [%0], [%1], 16;" :: "r"(dst), "l"(src))
#define CP_COMMIT() asm volatile("cp.async.commit_group;" ::: "memory")
#define CP_WAIT0()  asm volatile("cp.async.wait_group 0;" ::: "memory")
#define CP_WAIT1()  asm volatile("cp.async.wait_group 1;" ::: "memory")

// ============================================================
// prep: edge fp32 -> fp16, plus W conversions in first blocks
// ============================================================
__global__ void __launch_bounds__(256) prep_kernel(const float* __restrict__ E,
                                                   const float* __restrict__ Wk,
                                                   const float* __restrict__ We)
{
    size_t e0 = ((size_t)blockIdx.x * 256 + threadIdx.x) * 8;
    float4 f0 = *(const float4*)(E + e0);
    float4 f1 = *(const float4*)(E + e0 + 4);
    union { __half2 h[4]; uint4 u; } o;
    o.h[0] = __floats2half2_rn(f0.x, f0.y);
    o.h[1] = __floats2half2_rn(f0.z, f0.w);
    o.h[2] = __floats2half2_rn(f1.x, f1.y);
    o.h[3] = __floats2half2_rn(f1.z, f1.w);
    *(uint4*)(g_a16 + e0) = o.u;
    if (blockIdx.x < 256) {
        int t = blockIdx.x * 256 + threadIdx.x;    // 65536 W elements
        g_wk16[t] = __float2half_rn(Wk[t]);
        g_we16[t] = __float2half_rn(We[t]);
    }
}

// ============================================================
// fp16 tensor GEMM: C[131072,256] = act(A' @ W^T + bias)
// A' = A (MSG: scaled per (row, head=chunk) by g_msg, fused).
// SCORES: additionally emit S[b,h,m,n] = QK_SCALE * q . k from
// the fp32 accumulators (each warp's 32 cols = exactly 1 head).
// BM=64 BN=128 BK=32, 8 warps (warp tile 32x32), 3 CTAs/SM.
// ============================================================
#define ST_A    0
#define ST_B    5120
#define ST_MSG  15360
#define ST_SZ   15872
#define TG_SMEM (3 * ST_SZ)

template<bool MSG, bool OUT16, bool ACT, bool SCORES>
__global__ void __launch_bounds__(256, 3) tgemm_kernel(
    const __half* __restrict__ A, const __half* __restrict__ W,
    const float* __restrict__ bias, void* __restrict__ Cv)
{
    extern __shared__ char smem[];
    const uint32_t sb = smem_u32(smem);
    const int tid = threadIdx.x;
    const int wid = tid >> 5, lane = tid & 31;
    const int wm = wid >> 2, wn = wid & 3;      // warp tile rows wm*32, cols wn*32
    const int col0 = blockIdx.x * 128;
    const int r0 = blockIdx.y * 64;

    int mb_base = 0;
    if (MSG) {
        int b = r0 >> 14, m = (r0 >> 7) & 127, n0 = r0 & 127;
        mb_base = b * 131072 + m * 128 + n0;    // + c*16384 per chunk
    }

    float acc[2][4][4];
    #pragma unroll
    for (int i = 0; i < 2; i++)
        #pragma unroll
        for (int j = 0; j < 4; j++)
            #pragma unroll
            for (int q = 0; q < 4; q++) acc[i][j][q] = 0.f;

    const uint32_t aA = sb + ST_A + (wm * 32 + (lane & 15)) * 80 + (lane >> 4) * 16;
    const uint32_t bA = sb + ST_B +
        (wn * 32 + ((lane >> 4) & 1) * 8 + (lane & 7)) * 80 + ((lane >> 3) & 1) * 16;

    const int arow = tid >> 2, aq = tid & 3;    // A: 64 rows x 4 chunks

    auto fill = [&](int c, int stg) {
        uint32_t base = sb + stg * ST_SZ;
        CP16(base + ST_A + (uint32_t)(arow * 80 + aq * 16),
             (const char*)(A + (((size_t)(r0 + arow)) << 8) + c * 32 + aq * 8));
        #pragma unroll
        for (int u = 0; u < 2; u++) {
            int idx = tid + 256 * u;            // B: 128 rows x 4 chunks = 512
            int row = idx >> 2, q = idx & 3;
            CP16(base + ST_B + (uint32_t)(row * 80 + q * 16),
                 (const char*)(W + (((size_t)(col0 + row)) << 8) + c * 32 + q * 8));
        }
        if (MSG && tid < 16)
            CP16(base + ST_MSG + (uint32_t)(tid * 16),
                 (const char*)(g_msg + mb_base + c * 16384 + tid * 4));
        CP_COMMIT();
    };

    fill(0, 0);
    fill(1, 1);
    #pragma unroll 1
    for (int c = 0; c < 8; c++) {
        if (c < 7) CP_WAIT1(); else CP_WAIT0();
        __syncthreads();
        if (c < 6) fill(c + 2, (c + 2) % 3);
        const uint32_t soff = (uint32_t)((c % 3) * ST_SZ);

        // msg scales for this chunk (head == c).
        // mma m16n8k16 A-fragment: regs {a0,a2} hold row g=lane>>2,
        // regs {a1,a3} hold row g+8 (within each 16-row tile).
        __half2 s00, s01, s10, s11;
        if (MSG) {
            const float* sp = (const float*)(smem + (c % 3) * ST_SZ + ST_MSG);
            int g = lane >> 2;
            s00 = __half2half2(__float2half_rn(sp[wm * 32 + g]));
            s01 = __half2half2(__float2half_rn(sp[wm * 32 + g + 8]));
            s10 = __half2half2(__float2half_rn(sp[wm * 32 + 16 + g]));
            s11 = __half2half2(__float2half_rn(sp[wm * 32 + 16 + g + 8]));
        }

        const uint32_t ab = aA + soff;
        const uint32_t bb = bA + soff;
        #pragma unroll
        for (int ks = 0; ks < 2; ks++) {
            const uint32_t koff = ks * 32;
            uint32_t ah[8], bf[8];
            ldsm4(&ah[0], ab + koff);
            ldsm4(&ah[4], ab + 16 * 80 + koff);
            ldsm4(&bf[0], bb + koff);
            ldsm4(&bf[4], bb + 16 * 80 + koff);
            if (MSG) {
                __half2* h = reinterpret_cast<__half2*>(ah);
                h[0] = __hmul2(h[0], s00); h[2] = __hmul2(h[2], s00);
                h[1] = __hmul2(h[1], s01); h[3] = __hmul2(h[3], s01);
                h[4] = __hmul2(h[4], s10); h[6] = __hmul2(h[6], s10);
                h[5] = __hmul2(h[5], s11); h[7] = __hmul2(h[7], s11);
            }
            #pragma unroll
            for (int mt = 0; mt < 2; mt++)
                #pragma unroll
                for (int nt = 0; nt < 4; nt++)
                    mma_f16(acc[mt][nt], &ah[mt * 4], &bf[(nt >> 1) * 4 + (nt & 1) * 2]);
        }
    }

    // q values for fused scores (warp's 32 cols = head bx*4+wn)
    float qv[4][2];
    float dotR[4] = {0.f, 0.f, 0.f, 0.f};
    if (SCORES) {
        int b = r0 >> 14, m = (r0 >> 7) & 127;
        const float* qrow = g_q + (size_t)(b * 128 + m) * 256 + col0 + wn * 32 + (lane & 3) * 2;
        #pragma unroll
        for (int nt = 0; nt < 4; nt++) { qv[nt][0] = qrow[nt * 8]; qv[nt][1] = qrow[nt * 8 + 1]; }
    }

    // epilogue
    #pragma unroll
    for (int nt = 0; nt < 4; nt++) {
        const int col = col0 + wn * 32 + nt * 8 + (lane & 3) * 2;
        const float b0 = bias[col], b1 = bias[col + 1];
        #pragma unroll
        for (int mt = 0; mt < 2; mt++) {
            int row = r0 + wm * 32 + mt * 16 + (lane >> 2);
            float v0 = acc[mt][nt][0] + b0, v1 = acc[mt][nt][1] + b1;
            float v2 = acc[mt][nt][2] + b0, v3 = acc[mt][nt][3] + b1;
            if (SCORES) {
                dotR[2 * mt]     += v0 * qv[nt][0] + v1 * qv[nt][1];
                dotR[2 * mt + 1] += v2 * qv[nt][0] + v3 * qv[nt][1];
            }
            if (ACT) { v0 = mish_f(v0); v1 = mish_f(v1); v2 = mish_f(v2); v3 = mish_f(v3); }
            if (OUT16) {
                __half* C = (__half*)Cv;
                *(__half2*)(C + (size_t)row * 256 + col) = __floats2half2_rn(v0, v1);
                *(__half2*)(C + (size_t)(row + 8) * 256 + col) = __floats2half2_rn(v2, v3);
            } else {
                float* C = (float*)Cv;
                float2 p0; p0.x = v0; p0.y = v1;
                float2 p1; p1.x = v2; p1.y = v3;
                *(float2*)(C + (size_t)row * 256 + col) = p0;
                *(float2*)(C + (size_t)(row + 8) * 256 + col) = p1;
            }
        }
    }

    if (SCORES) {
        #pragma unroll
        for (int i = 0; i < 4; i++) {
            dotR[i] += __shfl_xor_sync(0xffffffffu, dotR[i], 1);
            dotR[i] += __shfl_xor_sync(0xffffffffu, dotR[i], 2);
        }
        if ((lane & 3) == 0) {
            int b = r0 >> 14, m = (r0 >> 7) & 127, n0 = r0 & 127;
            int h = blockIdx.x * 4 + wn;
            int g = lane >> 2;
            float* Sp = g_S + (((size_t)(b * 8 + h) * 128) + m) * 128 + n0 + wm * 32;
            Sp[g]      = dotR[0] * QK_SCALE;
            Sp[g + 8]  = dotR[1] * QK_SCALE;
            Sp[g + 16] = dotR[2] * QK_SCALE;
            Sp[g + 24] = dotR[3] * QK_SCALE;
        }
    }
}

// ============================================================
// fp32 SGEMM core for the small (1024-row) projections
// ============================================================
template<bool ACT>
__device__ __forceinline__ void gemm_core(
    const float* __restrict__ A, const float* __restrict__ W,
    const float* __restrict__ bias, float* __restrict__ C,
    int row0, int col0)
{
    __shared__ __align__(16) float As[16][132];
    __shared__ __align__(16) float Bs[16][68];

    const int t  = threadIdx.x;
    const int tx = t & 15;
    const int ty = t >> 4;
    const int lr = t >> 2;
    const int lc = (t & 3) << 2;
    const int gr1 = row0 + lr;
    const int gr2 = gr1 + 64;

    float acc[8][4];
    #pragma unroll
    for (int i = 0; i < 8; i++)
        #pragma unroll
        for (int j = 0; j < 4; j++) acc[i][j] = 0.f;

    for (int k0 = 0; k0 < HID; k0 += 16) {
        float4 a1 = *(const float4*)(A + (size_t)gr1 * HID + k0 + lc);
        float4 a2 = *(const float4*)(A + (size_t)gr2 * HID + k0 + lc);
        As[lc + 0][lr] = a1.x; As[lc + 1][lr] = a1.y;
        As[lc + 2][lr] = a1.z; As[lc + 3][lr] = a1.w;
        As[lc + 0][lr + 64] = a2.x; As[lc + 1][lr + 64] = a2.y;
        As[lc + 2][lr + 64] = a2.z; As[lc + 3][lr + 64] = a2.w;
        float4 b4 = *(const float4*)(W + (size_t)(col0 + lr) * HID + k0 + lc);
        Bs[lc + 0][lr] = b4.x; Bs[lc + 1][lr] = b4.y;
        Bs[lc + 2][lr] = b4.z; Bs[lc + 3][lr] = b4.w;
        __syncthreads();
        #pragma unroll
        for (int kk = 0; kk < 16; kk++) {
            float4 alo = *(const float4*)&As[kk][ty * 8];
            float4 ahi = *(const float4*)&As[kk][ty * 8 + 4];
            float4 bv  = *(const float4*)&Bs[kk][tx * 4];
            float avv[8] = {alo.x, alo.y, alo.z, alo.w, ahi.x, ahi.y, ahi.z, ahi.w};
            float bw[4] = {bv.x, bv.y, bv.z, bv.w};
            #pragma unroll
            for (int i = 0; i < 8; i++)
                #pragma unroll
                for (int j = 0; j < 4; j++)
                    acc[i][j] = fmaf(avv[i], bw[j], acc[i][j]);
        }
        __syncthreads();
    }

    float4 bb = *(const float4*)(bias + col0 + tx * 4);
    float bias4[4] = {bb.x, bb.y, bb.z, bb.w};
    #pragma unroll
    for (int i = 0; i < 8; i++) {
        float v0 = acc[i][0] + bias4[0];
        float v1 = acc[i][1] + bias4[1];
        float v2 = acc[i][2] + bias4[2];
        float v3 = acc[i][3] + bias4[3];
        if (ACT) { v0 = mish_f(v0); v1 = mish_f(v1); v2 = mish_f(v2); v3 = mish_f(v3); }
        float4 o; o.x = v0; o.y = v1; o.z = v2; o.w = v3;
        *(float4*)(C + (size_t)(row0 + ty * 8 + i) * HID + col0 + tx * 4) = o;
    }
}

__global__ void __launch_bounds__(256)
gemm_qv_kernel(const float* __restrict__ node,
               const float* __restrict__ Wq, const float* __restrict__ bq,
               const float* __restrict__ Wv, const float* __restrict__ bv,
               float* __restrict__ Cq, float* __restrict__ Cv)
{
    int by = blockIdx.y;
    if (by < 4) gemm_core<false>(node, Wq, bq, Cq, blockIdx.x * 128, by * 64);
    else        gemm_core<false>(node, Wv, bv, Cv, blockIdx.x * 128, (by - 4) * 64);
}

__global__ void __launch_bounds__(256)
gemm_node_kernel(const float* __restrict__ A, const float* __restrict__ W,
                 const float* __restrict__ bias, float* __restrict__ C)
{
    gemm_core<true>(A, W, bias, C, blockIdx.x * 128, blockIdx.y * 64);
}

// ============================================================
// Fused masked softmax stats + message
// ============================================================
#define SOFT_SMEM ((128 * 129 + 5 * 128) * 4)
__global__ void __launch_bounds__(256) softmsg_kernel(
    const float* __restrict__ dist, const float* __restrict__ mask,
    const float* __restrict__ lamp)
{
    extern __shared__ float Ss[];          // [128][129]
    float* rm  = Ss + 128 * 129;
    float* rs  = rm + 128;
    float* cm  = rs + 128;
    float* cs  = cm + 128;
    float* mks = cs + 128;
    const int bh = blockIdx.x, b = bh >> 3, t = threadIdx.x;
    const float lam = lamp[0];
    const float* Sg = g_S + (size_t)bh * 16384;

    if (t < 128) mks[t] = mask[b * 128 + t];
    #pragma unroll
    for (int rr = 0; rr < 16; rr++) {
        int idx4 = t + 256 * rr;
        int i = idx4 >> 5, j = (idx4 & 31) * 4;
        float4 v = *(const float4*)(Sg + i * 128 + j);
        float* d = Ss + i * 129 + j;
        d[0] = v.x; d[1] = v.y; d[2] = v.z; d[3] = v.w;
    }
    __syncthreads();

    if (t < 128) {
        const float* row = Ss + t * 129;
        float mx = -1e30f;
        #pragma unroll 4
        for (int j = 0; j < 128; j++) if (mks[j] != 0.f) mx = fmaxf(mx, row[j]);
        float sm = 0.f;
        #pragma unroll 4
        for (int j = 0; j < 128; j++) if (mks[j] != 0.f) sm += __expf(row[j] - mx);
        rm[t] = mx; rs[t] = 1.f / sm;
    } else {
        int m = t - 128;
        float mx = -1e30f;
        #pragma unroll 4
        for (int i = 0; i < 128; i++) if (mks[i] != 0.f) mx = fmaxf(mx, Ss[i * 129 + m]);
        float sm = 0.f;
        #pragma unroll 4
        for (int i = 0; i < 128; i++) if (mks[i] != 0.f) sm += __expf(Ss[i * 129 + m] - mx);
        cm[m] = mx; cs[m] = 1.f / sm;
    }
    __syncthreads();

    const float* db = dist + (size_t)b * 16384;
    float* mb = g_msg + (size_t)bh * 16384;
    #pragma unroll 1
    for (int r = 0; r < 64; r++) {
        int idx = t + 256 * r;
        int i = idx >> 7, j = idx & 127;
        float outv = 0.f;
        if (mks[j] != 0.f) {
            float o  = __expf(Ss[i * 129 + j] - rm[i]) * rs[i];
            float in = __expf(Ss[j * 129 + i] - cm[i]) * cs[i];
            float val = (i == j) ? in : (o + in);
            outv = val * __expf(-lam * db[idx]);
        }
        mb[idx] = outv;
    }
}

// ============================================================
__global__ void __launch_bounds__(256) nodeh_kernel()
{
    const int bh = blockIdx.x;
    const int b = bh >> 3, h = bh & 7;
    const int t = threadIdx.x;
    __shared__ __align__(16) float vs[128 * 32];
    #pragma unroll
    for (int r = 0; r < 4; r++) {
        int idx4 = t + 256 * r;
        int n = idx4 >> 3;
        int c = (idx4 & 7) * 4;
        *(float4*)&vs[n * 32 + c] =
            *(const float4*)(g_v + (size_t)(b * 128 + n) * 256 + h * 32 + c);
    }
    __syncthreads();
    const int m = t & 127;
    const int dbase = (t >> 7) * 16;
    const float* mrow = g_msg + (size_t)bh * 16384 + m * 128;
    float acc[16];
    #pragma unroll
    for (int d = 0; d < 16; d++) acc[d] = 0.f;
    for (int n = 0; n < 128; n++) {
        float w = mrow[n];
        const float* vr = &vs[n * 32 + dbase];
        #pragma unroll
        for (int d = 0; d < 16; d++) acc[d] = fmaf(w, vr[d], acc[d]);
    }
    float* outp = g_nodeh + (size_t)(b * 128 + m) * 256 + h * 32 + dbase;
    #pragma unroll
    for (int d = 0; d < 16; d++) outp[d] = acc[d];
}

// ============================================================
extern "C" void kernel_launch(void* const* d_in, const int* in_sizes, int n_in,
                              void* d_out, int out_size)
{
    const float* node = (const float*)d_in[0];
    const float* edge = (const float*)d_in[1];
    const float* dist = (const float*)d_in[2];
    const float* mask = (const float*)d_in[3];
    const float* lam  = (const float*)d_in[4];
    const float* Wq = (const float*)d_in[5];  const float* bq = (const float*)d_in[6];
    const float* Wk = (const float*)d_in[7];  const float* bk = (const float*)d_in[8];
    const float* Wv = (const float*)d_in[9];  const float* bv = (const float*)d_in[10];
    const float* Wn = (const float*)d_in[11]; const float* bn = (const float*)d_in[12];
    const float* We = (const float*)d_in[13]; const float* be = (const float*)d_in[14];

    float* out = (float*)d_out;
    float* node_out = out;
    float* edge_out = out + (size_t)NROWS_N * HID;

    float *pq, *pv, *pnh;
    __half *pa16, *pk16, *pwk16, *pwe16;
    cudaGetSymbolAddress((void**)&pq, g_q);
    cudaGetSymbolAddress((void**)&pv, g_v);
    cudaGetSymbolAddress((void**)&pnh, g_nodeh);
    cudaGetSymbolAddress((void**)&pa16, g_a16);
    cudaGetSymbolAddress((void**)&pk16, g_k16);
    cudaGetSymbolAddress((void**)&pwk16, g_wk16);
    cudaGetSymbolAddress((void**)&pwe16, g_we16);

    cudaFuncSetAttribute((const void*)tgemm_kernel<false, true, false, true>,
                         cudaFuncAttributeMaxDynamicSharedMemorySize, TG_SMEM);
    cudaFuncSetAttribute((const void*)tgemm_kernel<true, false, true, false>,
                         cudaFuncAttributeMaxDynamicSharedMemorySize, TG_SMEM);
    cudaFuncSetAttribute((const void*)softmsg_kernel,
                         cudaFuncAttributeMaxDynamicSharedMemorySize, SOFT_SMEM);

    dim3 gT(2, NROWS_E / 64);           // (2 col blocks, 2048 row blocks)

    prep_kernel<<<16384, 256>>>(edge, Wk, We);
    gemm_qv_kernel<<<dim3(8, 8), 256>>>(node, Wq, bq, Wv, bv, pq, pv);
    tgemm_kernel<false, true, false, true><<<gT, 256, TG_SMEM>>>(pa16, pwk16, bk, (void*)pk16);
    softmsg_kernel<<<64, 256, SOFT_SMEM>>>(dist, mask, lam);
    tgemm_kernel<true, false, true, false><<<gT, 256, TG_SMEM>>>(pk16, pwe16, be, edge_out);
    nodeh_kernel<<<64, 256>>>();
    gemm_node_kernel<<<dim3(8, 4), 256>>>(pnh, Wn, bn, node_out);
}

// round 10
// speedup vs baseline: 3.4888x; 1.1447x over previous
#include <cuda_runtime.h>
#include <cuda_fp16.h>
#include <math.h>
#include <cstdint>

#define Bb 8
#define Mm 128
#define HID 256
#define NROWS_E (Bb*Mm*Mm)   // 131072
#define NROWS_N (Bb*Mm)      // 1024
#define QK_SCALE 0.17677669529663687f  // 1/sqrt(32)

// -------- scratch (device globals) --------
__device__ __align__(16) __half g_k16[(size_t)NROWS_E * HID];  // 67 MB fp16 k
__device__ __align__(16) __half g_a16[(size_t)NROWS_E * HID];  // 67 MB fp16 edge
__device__ float g_q[NROWS_N * HID];
__device__ float g_v[NROWS_N * HID];
__device__ float g_S[64 * 128 * 128];
__device__ float g_St[64 * 128 * 128];        // transposed scores
__device__ float g_msg[64 * 128 * 128];
__device__ float g_nodeh[NROWS_N * HID];
__device__ float g_rmax[64 * 128];
__device__ float g_rsum[64 * 128];            // reciprocal
__device__ float g_cmax[64 * 128];
__device__ float g_csum[64 * 128];            // reciprocal
__device__ __align__(16) __half g_wk16[HID * HID];
__device__ __align__(16) __half g_we16[HID * HID];

__device__ __forceinline__ float mish_f(float x) {
    if (x > 20.f) return x;
    float t = 1.f + __expf(x);
    float t2 = t * t;
    return x * __fdividef(t2 - 1.f, t2 + 1.f);
}

__device__ __forceinline__ uint32_t smem_u32(const void* p) {
    uint32_t a;
    asm("{ .reg .u64 t; cvta.to.shared.u64 t, %1; cvt.u32.u64 %0, t; }" : "=r"(a) : "l"(p));
    return a;
}
__device__ __forceinline__ void ldsm4(uint32_t* r, uint32_t addr) {
    asm volatile("ldmatrix.sync.aligned.m8n8.x4.shared.b16 {%0,%1,%2,%3}, [%4];"
        : "=r"(r[0]), "=r"(r[1]), "=r"(r[2]), "=r"(r[3]) : "r"(addr));
}
__device__ __forceinline__ void mma_f16(float* d, const uint32_t* a, const uint32_t* b) {
    asm volatile("mma.sync.aligned.m16n8k16.row.col.f32.f16.f16.f32 "
        "{%0,%1,%2,%3}, {%4,%5,%6,%7}, {%8,%9}, {%0,%1,%2,%3};"
        : "+f"(d[0]), "+f"(d[1]), "+f"(d[2]), "+f"(d[3])
        : "r"(a[0]), "r"(a[1]), "r"(a[2]), "r"(a[3]), "r"(b[0]), "r"(b[1]));
}
#define CP16(dst, src) asm volatile("cp.async.cg.shared.global [%0], [%1], 16;" :: "r"(dst), "l"(src))
#define CP_COMMIT() asm volatile("cp.async.commit_group;" ::: "memory")
#define CP_WAIT0()  asm volatile("cp.async.wait_group 0;" ::: "memory")
#define CP_WAIT1()  asm volatile("cp.async.wait_group 1;" ::: "memory")

// ============================================================
// prep: edge fp32 -> fp16, plus W conversions in first blocks
// ============================================================
__global__ void __launch_bounds__(256) prep_kernel(const float* __restrict__ E,
                                                   const float* __restrict__ Wk,
                                                   const float* __restrict__ We)
{
    size_t e0 = ((size_t)blockIdx.x * 256 + threadIdx.x) * 8;
    float4 f0 = *(const float4*)(E + e0);
    float4 f1 = *(const float4*)(E + e0 + 4);
    union { __half2 h[4]; uint4 u; } o;
    o.h[0] = __floats2half2_rn(f0.x, f0.y);
    o.h[1] = __floats2half2_rn(f0.z, f0.w);
    o.h[2] = __floats2half2_rn(f1.x, f1.y);
    o.h[3] = __floats2half2_rn(f1.z, f1.w);
    *(uint4*)(g_a16 + e0) = o.u;
    if (blockIdx.x < 256) {
        int t = blockIdx.x * 256 + threadIdx.x;    // 65536 W elements
        g_wk16[t] = __float2half_rn(Wk[t]);
        g_we16[t] = __float2half_rn(We[t]);
    }
}

// ============================================================
// fp16 tensor GEMM: C[131072,256] = act(A' @ W^T + bias)
// A' = A (MSG: scaled per (row, head=chunk) by g_msg, fused).
// SCORES: emit S[b,h,m,n] AND St[b,h,n,m] from the accumulators.
// BM=64 BN=128 BK=32, 8 warps (warp tile 32x32), 3 CTAs/SM.
// ============================================================
#define ST_A    0
#define ST_B    5120
#define ST_MSG  15360
#define ST_SZ   15872
#define TG_SMEM (3 * ST_SZ)

template<bool MSG, bool OUT16, bool ACT, bool SCORES>
__global__ void __launch_bounds__(256, 3) tgemm_kernel(
    const __half* __restrict__ A, const __half* __restrict__ W,
    const float* __restrict__ bias, void* __restrict__ Cv)
{
    extern __shared__ char smem[];
    const uint32_t sb = smem_u32(smem);
    const int tid = threadIdx.x;
    const int wid = tid >> 5, lane = tid & 31;
    const int wm = wid >> 2, wn = wid & 3;      // warp tile rows wm*32, cols wn*32
    const int col0 = blockIdx.x * 128;
    const int r0 = blockIdx.y * 64;

    int mb_base = 0;
    if (MSG) {
        int b = r0 >> 14, m = (r0 >> 7) & 127, n0 = r0 & 127;
        mb_base = b * 131072 + m * 128 + n0;    // + c*16384 per chunk
    }

    float acc[2][4][4];
    #pragma unroll
    for (int i = 0; i < 2; i++)
        #pragma unroll
        for (int j = 0; j < 4; j++)
            #pragma unroll
            for (int q = 0; q < 4; q++) acc[i][j][q] = 0.f;

    const uint32_t aA = sb + ST_A + (wm * 32 + (lane & 15)) * 80 + (lane >> 4) * 16;
    const uint32_t bA = sb + ST_B +
        (wn * 32 + ((lane >> 4) & 1) * 8 + (lane & 7)) * 80 + ((lane >> 3) & 1) * 16;

    const int arow = tid >> 2, aq = tid & 3;    // A: 64 rows x 4 chunks

    auto fill = [&](int c, int stg) {
        uint32_t base = sb + stg * ST_SZ;
        CP16(base + ST_A + (uint32_t)(arow * 80 + aq * 16),
             (const char*)(A + (((size_t)(r0 + arow)) << 8) + c * 32 + aq * 8));
        #pragma unroll
        for (int u = 0; u < 2; u++) {
            int idx = tid + 256 * u;            // B: 128 rows x 4 chunks = 512
            int row = idx >> 2, q = idx & 3;
            CP16(base + ST_B + (uint32_t)(row * 80 + q * 16),
                 (const char*)(W + (((size_t)(col0 + row)) << 8) + c * 32 + q * 8));
        }
        if (MSG && tid < 16)
            CP16(base + ST_MSG + (uint32_t)(tid * 16),
                 (const char*)(g_msg + mb_base + c * 16384 + tid * 4));
        CP_COMMIT();
    };

    fill(0, 0);
    fill(1, 1);
    #pragma unroll 1
    for (int c = 0; c < 8; c++) {
        if (c < 7) CP_WAIT1(); else CP_WAIT0();
        __syncthreads();
        if (c < 6) fill(c + 2, (c + 2) % 3);
        const uint32_t soff = (uint32_t)((c % 3) * ST_SZ);

        // msg scales for this chunk (head == c).
        // mma m16n8k16 A-fragment: regs {a0,a2} hold row g=lane>>2,
        // regs {a1,a3} hold row g+8 (within each 16-row tile).
        __half2 s00, s01, s10, s11;
        if (MSG) {
            const float* sp = (const float*)(smem + (c % 3) * ST_SZ + ST_MSG);
            int g = lane >> 2;
            s00 = __half2half2(__float2half_rn(sp[wm * 32 + g]));
            s01 = __half2half2(__float2half_rn(sp[wm * 32 + g + 8]));
            s10 = __half2half2(__float2half_rn(sp[wm * 32 + 16 + g]));
            s11 = __half2half2(__float2half_rn(sp[wm * 32 + 16 + g + 8]));
        }

        const uint32_t ab = aA + soff;
        const uint32_t bb = bA + soff;
        #pragma unroll
        for (int ks = 0; ks < 2; ks++) {
            const uint32_t koff = ks * 32;
            uint32_t ah[8], bf[8];
            ldsm4(&ah[0], ab + koff);
            ldsm4(&ah[4], ab + 16 * 80 + koff);
            ldsm4(&bf[0], bb + koff);
            ldsm4(&bf[4], bb + 16 * 80 + koff);
            if (MSG) {
                __half2* h = reinterpret_cast<__half2*>(ah);
                h[0] = __hmul2(h[0], s00); h[2] = __hmul2(h[2], s00);
                h[1] = __hmul2(h[1], s01); h[3] = __hmul2(h[3], s01);
                h[4] = __hmul2(h[4], s10); h[6] = __hmul2(h[6], s10);
                h[5] = __hmul2(h[5], s11); h[7] = __hmul2(h[7], s11);
            }
            #pragma unroll
            for (int mt = 0; mt < 2; mt++)
                #pragma unroll
                for (int nt = 0; nt < 4; nt++)
                    mma_f16(acc[mt][nt], &ah[mt * 4], &bf[(nt >> 1) * 4 + (nt & 1) * 2]);
        }
    }

    // q values for fused scores (warp's 32 cols = head bx*4+wn)
    float qv[4][2];
    float dotR[4] = {0.f, 0.f, 0.f, 0.f};
    if (SCORES) {
        int b = r0 >> 14, m = (r0 >> 7) & 127;
        const float* qrow = g_q + (size_t)(b * 128 + m) * 256 + col0 + wn * 32 + (lane & 3) * 2;
        #pragma unroll
        for (int nt = 0; nt < 4; nt++) { qv[nt][0] = qrow[nt * 8]; qv[nt][1] = qrow[nt * 8 + 1]; }
    }

    // epilogue
    #pragma unroll
    for (int nt = 0; nt < 4; nt++) {
        const int col = col0 + wn * 32 + nt * 8 + (lane & 3) * 2;
        const float b0 = bias[col], b1 = bias[col + 1];
        #pragma unroll
        for (int mt = 0; mt < 2; mt++) {
            int row = r0 + wm * 32 + mt * 16 + (lane >> 2);
            float v0 = acc[mt][nt][0] + b0, v1 = acc[mt][nt][1] + b1;
            float v2 = acc[mt][nt][2] + b0, v3 = acc[mt][nt][3] + b1;
            if (SCORES) {
                dotR[2 * mt]     += v0 * qv[nt][0] + v1 * qv[nt][1];
                dotR[2 * mt + 1] += v2 * qv[nt][0] + v3 * qv[nt][1];
            }
            if (ACT) { v0 = mish_f(v0); v1 = mish_f(v1); v2 = mish_f(v2); v3 = mish_f(v3); }
            if (OUT16) {
                __half* C = (__half*)Cv;
                *(__half2*)(C + (size_t)row * 256 + col) = __floats2half2_rn(v0, v1);
                *(__half2*)(C + (size_t)(row + 8) * 256 + col) = __floats2half2_rn(v2, v3);
            } else {
                float* C = (float*)Cv;
                float2 p0; p0.x = v0; p0.y = v1;
                float2 p1; p1.x = v2; p1.y = v3;
                *(float2*)(C + (size_t)row * 256 + col) = p0;
                *(float2*)(C + (size_t)(row + 8) * 256 + col) = p1;
            }
        }
    }

    if (SCORES) {
        #pragma unroll
        for (int i = 0; i < 4; i++) {
            dotR[i] += __shfl_xor_sync(0xffffffffu, dotR[i], 1);
            dotR[i] += __shfl_xor_sync(0xffffffffu, dotR[i], 2);
        }
        if ((lane & 3) == 0) {
            int b = r0 >> 14, m = (r0 >> 7) & 127, n0 = r0 & 127;
            int h = blockIdx.x * 4 + wn;
            int g = lane >> 2;
            float s0 = dotR[0] * QK_SCALE, s1 = dotR[1] * QK_SCALE;
            float s2 = dotR[2] * QK_SCALE, s3 = dotR[3] * QK_SCALE;
            float* Sp = g_S + (((size_t)(b * 8 + h) * 128) + m) * 128 + n0 + wm * 32;
            Sp[g] = s0; Sp[g + 8] = s1; Sp[g + 16] = s2; Sp[g + 24] = s3;
            float* Stp = g_St + (((size_t)(b * 8 + h) * 128) + n0 + wm * 32) * 128 + m;
            Stp[(size_t)g * 128] = s0;
            Stp[(size_t)(g + 8) * 128] = s1;
            Stp[(size_t)(g + 16) * 128] = s2;
            Stp[(size_t)(g + 24) * 128] = s3;
        }
    }
}

// ============================================================
// fp32 SGEMM core for the small (1024-row) projections
// ============================================================
template<bool ACT>
__device__ __forceinline__ void gemm_core(
    const float* __restrict__ A, const float* __restrict__ W,
    const float* __restrict__ bias, float* __restrict__ C,
    int row0, int col0)
{
    __shared__ __align__(16) float As[16][132];
    __shared__ __align__(16) float Bs[16][68];

    const int t  = threadIdx.x;
    const int tx = t & 15;
    const int ty = t >> 4;
    const int lr = t >> 2;
    const int lc = (t & 3) << 2;
    const int gr1 = row0 + lr;
    const int gr2 = gr1 + 64;

    float acc[8][4];
    #pragma unroll
    for (int i = 0; i < 8; i++)
        #pragma unroll
        for (int j = 0; j < 4; j++) acc[i][j] = 0.f;

    for (int k0 = 0; k0 < HID; k0 += 16) {
        float4 a1 = *(const float4*)(A + (size_t)gr1 * HID + k0 + lc);
        float4 a2 = *(const float4*)(A + (size_t)gr2 * HID + k0 + lc);
        As[lc + 0][lr] = a1.x; As[lc + 1][lr] = a1.y;
        As[lc + 2][lr] = a1.z; As[lc + 3][lr] = a1.w;
        As[lc + 0][lr + 64] = a2.x; As[lc + 1][lr + 64] = a2.y;
        As[lc + 2][lr + 64] = a2.z; As[lc + 3][lr + 64] = a2.w;
        float4 b4 = *(const float4*)(W + (size_t)(col0 + lr) * HID + k0 + lc);
        Bs[lc + 0][lr] = b4.x; Bs[lc + 1][lr] = b4.y;
        Bs[lc + 2][lr] = b4.z; Bs[lc + 3][lr] = b4.w;
        __syncthreads();
        #pragma unroll
        for (int kk = 0; kk < 16; kk++) {
            float4 alo = *(const float4*)&As[kk][ty * 8];
            float4 ahi = *(const float4*)&As[kk][ty * 8 + 4];
            float4 bv  = *(const float4*)&Bs[kk][tx * 4];
            float avv[8] = {alo.x, alo.y, alo.z, alo.w, ahi.x, ahi.y, ahi.z, ahi.w};
            float bw[4] = {bv.x, bv.y, bv.z, bv.w};
            #pragma unroll
            for (int i = 0; i < 8; i++)
                #pragma unroll
                for (int j = 0; j < 4; j++)
                    acc[i][j] = fmaf(avv[i], bw[j], acc[i][j]);
        }
        __syncthreads();
    }

    float4 bb = *(const float4*)(bias + col0 + tx * 4);
    float bias4[4] = {bb.x, bb.y, bb.z, bb.w};
    #pragma unroll
    for (int i = 0; i < 8; i++) {
        float v0 = acc[i][0] + bias4[0];
        float v1 = acc[i][1] + bias4[1];
        float v2 = acc[i][2] + bias4[2];
        float v3 = acc[i][3] + bias4[3];
        if (ACT) { v0 = mish_f(v0); v1 = mish_f(v1); v2 = mish_f(v2); v3 = mish_f(v3); }
        float4 o; o.x = v0; o.y = v1; o.z = v2; o.w = v3;
        *(float4*)(C + (size_t)(row0 + ty * 8 + i) * HID + col0 + tx * 4) = o;
    }
}

__global__ void __launch_bounds__(256)
gemm_qv_kernel(const float* __restrict__ node,
               const float* __restrict__ Wq, const float* __restrict__ bq,
               const float* __restrict__ Wv, const float* __restrict__ bv,
               float* __restrict__ Cq, float* __restrict__ Cv)
{
    int by = blockIdx.y;
    if (by < 4) gemm_core<false>(node, Wq, bq, Cq, blockIdx.x * 128, by * 64);
    else        gemm_core<false>(node, Wv, bv, Cv, blockIdx.x * 128, (by - 4) * 64);
}

__global__ void __launch_bounds__(256)
gemm_node_kernel(const float* __restrict__ A, const float* __restrict__ W,
                 const float* __restrict__ bias, float* __restrict__ C)
{
    gemm_core<true>(A, W, bias, C, blockIdx.x * 128, blockIdx.y * 64);
}

// ============================================================
// stats: one warp per (kind, bh, i).
// kind 0: row stats over S[bh,i,:]; kind 1: col stats over St[bh,i,:].
// ============================================================
__global__ void __launch_bounds__(256) stats_kernel(const float* __restrict__ mask)
{
    const int id = blockIdx.x * 8 + (threadIdx.x >> 5);   // 0..16383
    const int lane = threadIdx.x & 31;
    const int kind = id >> 13;
    const int rem = id & 8191;
    const int bh = rem >> 7, i = rem & 127, b = bh >> 3;

    const float* src = (kind ? g_St : g_S) + (size_t)bh * 16384 + i * 128 + lane * 4;
    float4 v = *(const float4*)src;
    float4 mk = *(const float4*)(mask + b * 128 + lane * 4);

    float x0 = (mk.x != 0.f) ? v.x : -1e30f;
    float x1 = (mk.y != 0.f) ? v.y : -1e30f;
    float x2 = (mk.z != 0.f) ? v.z : -1e30f;
    float x3 = (mk.w != 0.f) ? v.w : -1e30f;
    float mx = fmaxf(fmaxf(x0, x1), fmaxf(x2, x3));
    #pragma unroll
    for (int s = 16; s > 0; s >>= 1) mx = fmaxf(mx, __shfl_xor_sync(0xffffffffu, mx, s));

    float sm = ((mk.x != 0.f) ? __expf(x0 - mx) : 0.f)
             + ((mk.y != 0.f) ? __expf(x1 - mx) : 0.f)
             + ((mk.z != 0.f) ? __expf(x2 - mx) : 0.f)
             + ((mk.w != 0.f) ? __expf(x3 - mx) : 0.f);
    #pragma unroll
    for (int s = 16; s > 0; s >>= 1) sm += __shfl_xor_sync(0xffffffffu, sm, s);

    if (lane == 0) {
        if (kind) { g_cmax[bh * 128 + i] = mx; g_csum[bh * 128 + i] = 1.f / sm; }
        else      { g_rmax[bh * 128 + i] = mx; g_rsum[bh * 128 + i] = 1.f / sm; }
    }
}

// ============================================================
// message: elementwise, fully coalesced via S and St.
// msg[i,j] = ((i==j ? in : o+in)) * exp(-lam*dist) * (mask_j!=0)
// ============================================================
__global__ void __launch_bounds__(256) message_kernel(
    const float* __restrict__ dist, const float* __restrict__ mask,
    const float* __restrict__ lamp)
{
    const int bh = blockIdx.x, b = bh >> 3, t = threadIdx.x;
    const int base = blockIdx.y * 2048;
    const float lam = lamp[0];
    __shared__ float mks[128];
    if (t < 128) mks[t] = mask[b * 128 + t];
    __syncthreads();

    const float* Sp  = g_S  + (size_t)bh * 16384;
    const float* Stp = g_St + (size_t)bh * 16384;
    const float* db  = dist + (size_t)b * 16384;
    float* mb = g_msg + (size_t)bh * 16384;

    #pragma unroll
    for (int r = 0; r < 8; r++) {
        int idx = base + t + 256 * r;
        int i = idx >> 7, j = idx & 127;
        float outv = 0.f;
        if (mks[j] != 0.f) {
            float o  = __expf(Sp[idx]  - g_rmax[bh * 128 + i]) * g_rsum[bh * 128 + i];
            float in = __expf(Stp[idx] - g_cmax[bh * 128 + i]) * g_csum[bh * 128 + i];
            float val = (i == j) ? in : (o + in);
            outv = val * __expf(-lam * db[idx]);
        }
        mb[idx] = outv;
    }
}

// ============================================================
// node_hidden: msg tile staged in padded smem (conflict-free)
// ============================================================
#define NODEH_SMEM ((128 * 32 + 128 * 129) * 4)
__global__ void __launch_bounds__(256) nodeh_kernel()
{
    extern __shared__ float sm_[];
    float* vs = sm_;              // 128 x 32
    float* ms = sm_ + 128 * 32;   // 128 x 129 (padded)
    const int bh = blockIdx.x;
    const int b = bh >> 3, h = bh & 7;
    const int t = threadIdx.x;
    #pragma unroll
    for (int r = 0; r < 4; r++) {
        int idx4 = t + 256 * r;
        int n = idx4 >> 3;
        int c = (idx4 & 7) * 4;
        *(float4*)&vs[n * 32 + c] =
            *(const float4*)(g_v + (size_t)(b * 128 + n) * 256 + h * 32 + c);
    }
    #pragma unroll
    for (int r = 0; r < 16; r++) {
        int idx4 = t + 256 * r;                 // 4096 float4s
        int i = idx4 >> 5, j = (idx4 & 31) * 4;
        float4 v = *(const float4*)(g_msg + (size_t)bh * 16384 + i * 128 + j);
        float* d = ms + i * 129 + j;
        d[0] = v.x; d[1] = v.y; d[2] = v.z; d[3] = v.w;
    }
    __syncthreads();
    const int m = t & 127;
    const int dbase = (t >> 7) * 16;
    const float* mrow = ms + m * 129;
    float acc[16];
    #pragma unroll
    for (int d = 0; d < 16; d++) acc[d] = 0.f;
    for (int n = 0; n < 128; n++) {
        float w = mrow[n];
        const float* vr = &vs[n * 32 + dbase];
        #pragma unroll
        for (int d = 0; d < 16; d++) acc[d] = fmaf(w, vr[d], acc[d]);
    }
    float* outp = g_nodeh + (size_t)(b * 128 + m) * 256 + h * 32 + dbase;
    #pragma unroll
    for (int d = 0; d < 16; d++) outp[d] = acc[d];
}

// ============================================================
extern "C" void kernel_launch(void* const* d_in, const int* in_sizes, int n_in,
                              void* d_out, int out_size)
{
    const float* node = (const float*)d_in[0];
    const float* edge = (const float*)d_in[1];
    const float* dist = (const float*)d_in[2];
    const float* mask = (const float*)d_in[3];
    const float* lam  = (const float*)d_in[4];
    const float* Wq = (const float*)d_in[5];  const float* bq = (const float*)d_in[6];
    const float* Wk = (const float*)d_in[7];  const float* bk = (const float*)d_in[8];
    const float* Wv = (const float*)d_in[9];  const float* bv = (const float*)d_in[10];
    const float* Wn = (const float*)d_in[11]; const float* bn = (const float*)d_in[12];
    const float* We = (const float*)d_in[13]; const float* be = (const float*)d_in[14];

    float* out = (float*)d_out;
    float* node_out = out;
    float* edge_out = out + (size_t)NROWS_N * HID;

    float *pq, *pv, *pnh;
    __half *pa16, *pk16, *pwk16, *pwe16;
    cudaGetSymbolAddress((void**)&pq, g_q);
    cudaGetSymbolAddress((void**)&pv, g_v);
    cudaGetSymbolAddress((void**)&pnh, g_nodeh);
    cudaGetSymbolAddress((void**)&pa16, g_a16);
    cudaGetSymbolAddress((void**)&pk16, g_k16);
    cudaGetSymbolAddress((void**)&pwk16, g_wk16);
    cudaGetSymbolAddress((void**)&pwe16, g_we16);

    cudaFuncSetAttribute((const void*)tgemm_kernel<false, true, false, true>,
                         cudaFuncAttributeMaxDynamicSharedMemorySize, TG_SMEM);
    cudaFuncSetAttribute((const void*)tgemm_kernel<true, false, true, false>,
                         cudaFuncAttributeMaxDynamicSharedMemorySize, TG_SMEM);
    cudaFuncSetAttribute((const void*)nodeh_kernel,
                         cudaFuncAttributeMaxDynamicSharedMemorySize, NODEH_SMEM);

    dim3 gT(2, NROWS_E / 64);           // (2 col blocks, 2048 row blocks)

    prep_kernel<<<16384, 256>>>(edge, Wk, We);
    gemm_qv_kernel<<<dim3(8, 8), 256>>>(node, Wq, bq, Wv, bv, pq, pv);
    tgemm_kernel<false, true, false, true><<<gT, 256, TG_SMEM>>>(pa16, pwk16, bk, (void*)pk16);
    stats_kernel<<<2048, 256>>>(mask);
    message_kernel<<<dim3(64, 8), 256>>>(dist, mask, lam);
    tgemm_kernel<true, false, true, false><<<gT, 256, TG_SMEM>>>(pk16, pwe16, be, edge_out);
    nodeh_kernel<<<64, 256, NODEH_SMEM>>>();
    gemm_node_kernel<<<dim3(8, 4), 256>>>(pnh, Wn, bn, node_out);
}